// round 14
// baseline (speedup 1.0000x reference)
#include <cuda_runtime.h>
#include <cuda_fp16.h>
#include <math.h>
#include <stdint.h>

#define BDIM 2048
#define HDIM 1024
#define BH (BDIM * HDIM)
#define HH ((size_t)HDIM * HDIM)

// ---------------- fp32 scratch pool ----------------------------------------
enum {
    P_XSL  = 0,   // 3
    P_HSR0 = 3,
    P_HSR1 = 4,
    P_Z1   = 5,
    P_R    = 6,
    P_HSL  = 7,   // 3
    P_RR   = 10,  // 3
    P_Z1R  = 13,  // 3
    P_RH   = 16,
    P_OMZ  = 17,
    P_Z2H  = 18,
    P_RHR  = 19,  // 3
    P_OMZR = 22,  // 3
    P_HT   = 25,
    P_HTL  = 26,  // 3
    P_ZH   = 29,
    P_ZHL  = 30,  // 3
    P_Z2HR = 33,  // 3
    P_TOTAL = 36
};
__device__ float g_pool[(size_t)P_TOTAL * BH];

// fp16 hi/lo activation slots, PACKED-FRAGMENT layout (see atoff)
enum {
    A_XH = 0, A_XL, A_HPH, A_HPL, A_Z1H, A_Z1L, A_RHI, A_RLO,
    A_RHH, A_RHL, A_OMZH, A_OMZL, A_HTH, A_HTL, A_ZHH, A_ZHL,
    A_Z2HH, A_Z2HL, A_TOTAL
};
__device__ __half g_act[(size_t)A_TOTAL * BH];

// transposed fp16 hi/lo weights, tiled+swizzled layout: mat m 0..5 (L0..2,R0..2)
__device__ __half g_wt[(size_t)12 * HH];

// B tiled layout (unchanged): element (row, h) -> kchunk region of [1024][32],
// 64B rows, 16B chunks swizzled: chunk' = chunk ^ ((row>>1)&3).
__device__ __forceinline__ size_t toff(int row, int h, int rows) {
    return (size_t)(h >> 5) * ((size_t)rows * 32) + (size_t)row * 32 +
           (size_t)((((h >> 3) & 3) ^ ((row >> 1) & 3)) << 3) + (h & 7);
}

// A packed-fragment layout: mma.m16n8k16 A-fragment order so GEMM loads one
// LDG.128 per (lane, tile). Tile = (kc, rb, wr, ks, mf) = 16x16 fp16.
// lane = (rr&7)*4 + ((c16&7)>>1); reg = (rr>>3) + ((c16>>3)<<1); half = c16&1.
__device__ __forceinline__ size_t atoff(int R, int h) {
    int kc = h >> 5, ks = (h >> 4) & 1, c16 = h & 15;
    int rb = R >> 7, wr = (R >> 6) & 1, mf = (R >> 4) & 3, rr = R & 15;
    int lane = (rr & 7) * 4 + ((c16 & 7) >> 1);
    int reg  = (rr >> 3) + ((c16 >> 3) << 1);
    size_t tile = (((size_t)(kc * 16 + rb) * 2 + wr) * 2 + ks) * 4 + mf;
    return tile * 256 + (size_t)lane * 8 + reg * 2 + (c16 & 1);
}

// ======================= PTX helpers ========================================
__device__ __forceinline__ uint32_t smem_u32(const void* p) {
    uint32_t a;
    asm("{ .reg .u64 t; cvta.to.shared.u64 t, %1; cvt.u32.u64 %0, t; }"
        : "=r"(a) : "l"(p));
    return a;
}

#define MBARRIER_INIT(mbar, count) \
    asm volatile("mbarrier.init.shared.b64 [%0], %1;" \
                 :: "r"((uint32_t)(mbar)), "r"((uint32_t)(count)) : "memory")

#define MBARRIER_EXPECT_TX(mbar, bytes) \
    asm volatile("mbarrier.arrive.expect_tx.shared.b64 _, [%0], %1;" \
                 :: "r"((uint32_t)(mbar)), "r"((uint32_t)(bytes)) : "memory")

#define MBARRIER_ARRIVE(mbar) \
    asm volatile("mbarrier.arrive.shared.b64 _, [%0];" \
                 :: "r"((uint32_t)(mbar)) : "memory")

#define MBARRIER_WAIT_PARITY(mbar, parity) do {                                   \
    uint32_t _m = (uint32_t)(mbar);                                               \
    uint32_t _p = (uint32_t)(parity);                                             \
    asm volatile(                                                                 \
        "{\n\t.reg .pred P1;\n\t"                                                 \
        "WAIT_LOOP_%=:\n\t"                                                       \
        "mbarrier.try_wait.parity.acquire.cta.shared::cta.b64 P1, [%0], %1, 0x989680;\n\t" \
        "@P1 bra.uni WAIT_DONE_%=;\n\t"                                           \
        "bra.uni WAIT_LOOP_%=;\n\t"                                               \
        "WAIT_DONE_%=:\n\t}"                                                      \
        :: "r"(_m), "r"(_p) : "memory");                                          \
} while (0)

__device__ __forceinline__ void bulk_g2s(uint32_t smem, const void* g,
                                         uint32_t bytes, uint32_t mbar) {
    asm volatile(
        "cp.async.bulk.shared::cluster.global.mbarrier::complete_tx::bytes "
        "[%0], [%1], %2, [%3];"
        :: "r"(smem), "l"(g), "r"(bytes), "r"(mbar) : "memory");
}

__device__ __forceinline__ void ldm_x4(uint32_t* r, uint32_t addr) {
    asm volatile("ldmatrix.sync.aligned.m8n8.x4.shared.b16 {%0,%1,%2,%3}, [%4];"
                 : "=r"(r[0]), "=r"(r[1]), "=r"(r[2]), "=r"(r[3]) : "r"(addr));
}

__device__ __forceinline__ void mma_f16(float* c, const uint32_t* a,
                                        uint32_t b0, uint32_t b1) {
    asm volatile(
        "mma.sync.aligned.m16n8k16.row.col.f32.f16.f16.f32 "
        "{%0,%1,%2,%3}, {%4,%5,%6,%7}, {%8,%9}, {%0,%1,%2,%3};"
        : "+f"(c[0]), "+f"(c[1]), "+f"(c[2]), "+f"(c[3])
        : "r"(a[0]), "r"(a[1]), "r"(a[2]), "r"(a[3]), "r"(b0), "r"(b1));
}

// ======================= GEMM: LDG-fragment A, bulk+LDSM B ==================
// C = (Ahi+Alo) @ (Bhi+Blo)^T, 3 passes (drop lo*lo), fp16, f32 accum.
// A: packed fragments in gmem, loaded per-lane with LDG.128 (LSU pipe).
// B: tiled+swizzled, bulk-copied to smem ring, loaded with ldmatrix.
struct Job {
    const __half* Ah; const __half* Al;
    const __half* Bh; const __half* Bl;
    float* C;
};
struct JobBatch { Job j[9]; };

#define KITERS  32
#define RGNB    8192u          // B: 128 rows * 64B
#define STAGEB  16384u         // Bh + Bl
#define NSTAGE  3
#define GSMEM   (128 + NSTAGE * 16384)

__global__ void __launch_bounds__(256, 2) gemm_mma(JobBatch batch) {
    extern __shared__ char dsm[];
    const Job job = batch.j[blockIdx.z];
    const int tid  = threadIdx.x;
    const int lane = tid & 31;
    const int wid  = tid >> 5;
    const int rb = blockIdx.y;
    const int m0 = rb * 128, n0 = blockIdx.x * 128;
    const int wm = (wid & 1) * 64;     // warp M offset
    const int wn = (wid >> 1) * 32;    // warp N offset
    const int wr = wid & 1;

    const uint32_t sb  = smem_u32(dsm);
    const uint32_t stg = sb + 128;

    if (tid == 0) {
#pragma unroll
        for (int s = 0; s < NSTAGE; s++) {
            MBARRIER_INIT(sb + s * 16, 1);      // full: tx-based
            MBARRIER_INIT(sb + s * 16 + 8, 8);  // empty: one arrive per warp
        }
    }
    __syncthreads();

    auto issue = [&](uint32_t sOff, int kc) {
        uint32_t dst = stg + sOff * STAGEB;
        uint32_t bar = sb + sOff * 16;
        MBARRIER_EXPECT_TX(bar, STAGEB);
        size_t bo = (size_t)kc * (1024 * 32) + (size_t)n0 * 32;
        bulk_g2s(dst,        job.Bh + bo, RGNB, bar);
        bulk_g2s(dst + RGNB, job.Bl + bo, RGNB, bar);
    };

    float acc[4][4][4];
#pragma unroll
    for (int i = 0; i < 4; i++)
#pragma unroll
        for (int j = 0; j < 4; j++)
#pragma unroll
            for (int q = 0; q < 4; q++) acc[i][j][q] = 0.f;

    if (tid == 0) { issue(0, 0); issue(1, 1); issue(2, 2); }

    uint32_t s = 0;
    int phase = 0;

#pragma unroll 1
    for (int it = 0; it < KITERS; ++it) {
        MBARRIER_WAIT_PARITY(sb + s * 16, phase);

        const uint32_t base = stg + s * STAGEB;
#pragma unroll
        for (int ks = 0; ks < 2; ks++) {
            // A fragment base for (it, rb, wr, ks): tile stride mf = 256 halves
            const size_t tb = ((((size_t)(it * 16 + rb) * 2 + wr) * 2 + ks) * 4) * 256
                              + (size_t)lane * 8;
            const uint4* __restrict__ pah = (const uint4*)(job.Ah + tb);
            const uint4* __restrict__ pal = (const uint4*)(job.Al + tb);

            // B fragments (hi & lo) via ldmatrix
            uint32_t bh[2][4], bl[2][4];
#pragma unroll
            for (int p = 0; p < 2; p++) {
                int r = wn + p * 16 + ((lane >> 4) & 1) * 8 + (lane & 7);
                int c = ks * 2 + ((lane >> 3) & 1);
                uint32_t off = (uint32_t)r * 64u +
                               (uint32_t)((c ^ ((r >> 1) & 3)) << 4);
                ldm_x4(bh[p], base + off);
                ldm_x4(bl[p], base + RGNB + off);
            }
            // mf-pair blocking: A fragments via LDG.128 (mf stride = 32 uint4)
#pragma unroll
            for (int mfp = 0; mfp < 2; mfp++) {
                uint4 ah0 = pah[(mfp * 2 + 0) * 32];
                uint4 ah1 = pah[(mfp * 2 + 1) * 32];
                uint4 al0 = pal[(mfp * 2 + 0) * 32];
                uint4 al1 = pal[(mfp * 2 + 1) * 32];
                const uint32_t* ahr[2] = {(const uint32_t*)&ah0, (const uint32_t*)&ah1};
                const uint32_t* alr[2] = {(const uint32_t*)&al0, (const uint32_t*)&al1};
#pragma unroll
                for (int q = 0; q < 2; q++)
#pragma unroll
                    for (int nf = 0; nf < 4; nf++)
                        mma_f16(acc[mfp * 2 + q][nf], ahr[q],
                                bh[nf >> 1][(nf & 1) * 2], bh[nf >> 1][(nf & 1) * 2 + 1]);
#pragma unroll
                for (int q = 0; q < 2; q++)
#pragma unroll
                    for (int nf = 0; nf < 4; nf++)
                        mma_f16(acc[mfp * 2 + q][nf], alr[q],
                                bh[nf >> 1][(nf & 1) * 2], bh[nf >> 1][(nf & 1) * 2 + 1]);
#pragma unroll
                for (int q = 0; q < 2; q++)
#pragma unroll
                    for (int nf = 0; nf < 4; nf++)
                        mma_f16(acc[mfp * 2 + q][nf], ahr[q],
                                bl[nf >> 1][(nf & 1) * 2], bl[nf >> 1][(nf & 1) * 2 + 1]);
            }
        }
        if (lane == 0) MBARRIER_ARRIVE(sb + s * 16 + 8);
        if (tid == 0 && it + NSTAGE < KITERS) {
            MBARRIER_WAIT_PARITY(sb + s * 16 + 8, phase);
            issue(s, it + NSTAGE);
        }
        if (++s == NSTAGE) { s = 0; phase ^= 1; }
    }

    // epilogue: direct f32 stores
    float* C = job.C + (size_t)m0 * HDIM + n0;
    const int r4 = lane >> 2, c2 = (lane & 3) * 2;
#pragma unroll
    for (int mf = 0; mf < 4; mf++)
#pragma unroll
        for (int nf = 0; nf < 4; nf++) {
            float* p0 = C + (size_t)(wm + mf * 16 + r4) * HDIM + wn + nf * 8 + c2;
            *(float2*)p0 = make_float2(acc[mf][nf][0], acc[mf][nf][1]);
            *(float2*)(p0 + 8 * HDIM) = make_float2(acc[mf][nf][2], acc[mf][nf][3]);
        }
}

// ---------------- weight transpose + fp16 hi/lo (B tiled layout) ------------
__global__ void wsplit_kernel(const float* __restrict__ L, const float* __restrict__ R,
                              __half* __restrict__ wt) {
    __shared__ float s[32][33];
    const int m = blockIdx.z;  // 0..5
    const float* W = (m < 3) ? (L + (size_t)m * HH) : (R + (size_t)(m - 3) * HH);
    __half* dh = wt + (size_t)(2 * m) * HH;
    __half* dl = wt + (size_t)(2 * m + 1) * HH;
    const int k0 = blockIdx.y * 32, n0 = blockIdx.x * 32;
    const int tx = threadIdx.x, ty = threadIdx.y;
#pragma unroll
    for (int j = 0; j < 32; j += 8)
        s[ty + j][tx] = W[(size_t)(k0 + ty + j) * HDIM + n0 + tx];
    __syncthreads();
#pragma unroll
    for (int j = 0; j < 32; j += 8) {
        float v = s[tx][ty + j];
        __half h = __float2half(v);
        size_t o = toff(n0 + ty + j, k0 + tx, 1024);
        dh[o] = h;
        dl[o] = __float2half(v - __half2float(h));
    }
}

// ---------------- activation fp16 split (packed-frag layout), 2 tensors -----
__global__ void asplit2_kernel(const float* __restrict__ a0,
                               __half* __restrict__ hi0, __half* __restrict__ lo0,
                               const float* __restrict__ a1,
                               __half* __restrict__ hi1, __half* __restrict__ lo1) {
    int i = blockIdx.x * 256 + threadIdx.x;
    if (i >= BH) return;
    const float* a = blockIdx.y ? a1 : a0;
    __half* hi = blockIdx.y ? hi1 : hi0;
    __half* lo = blockIdx.y ? lo1 : lo0;
    float v = a[i];
    __half h = __float2half(v);
    size_t o = atoff(i >> 10, i & 1023);
    hi[o] = h;
    lo[o] = __float2half(v - __half2float(h));
}

// ---------------- fused double sigmoid (+ packed splits) --------------------
__global__ void sig_kernel(const float* __restrict__ xsL0, const float* __restrict__ hsR0,
                           const float* __restrict__ xsL1, const float* __restrict__ hsR1,
                           const float* __restrict__ bias,
                           float* __restrict__ z1, float* __restrict__ r,
                           __half* __restrict__ z1h, __half* __restrict__ z1l,
                           __half* __restrict__ rh, __half* __restrict__ rl) {
    int i = blockIdx.x * blockDim.x + threadIdx.x;
    if (i >= BH) return;
    int h = i & (HDIM - 1);
    float t0 = xsL0[i] + hsR0[i] + bias[h];
    float t1 = xsL1[i] + hsR1[i] + bias[HDIM + h];
    float v0 = 1.f / (1.f + expf(-t0));
    float v1 = 1.f / (1.f + expf(-t1));
    z1[i] = v0; r[i] = v1;
    size_t o = atoff(i >> 10, h);
    __half h0 = __float2half(v0);
    __half h1 = __float2half(v1);
    z1h[o] = h0; z1l[o] = __float2half(v0 - __half2float(h0));
    rh[o]  = h1; rl[o]  = __float2half(v1 - __half2float(h1));
}

// ---------------- mix kernels -----------------------------------------------
enum { MIX_MUL = 0, MIX_ADD = 1, MIX_ONEMINUS = 2, MIX_TANH = 3 };

template <int OP>
__device__ __forceinline__ void mix_body(
    int brow, int tid,
    const float* __restrict__ A3, const float* __restrict__ B3,
    const float* __restrict__ a3, const float* __restrict__ b3,
    const float* __restrict__ bias, const float* __restrict__ w,
    float* __restrict__ out,
    __half* __restrict__ oh, __half* __restrict__ ol,
    float* gout, int gcol,
    float* cs, float (*red)[8], float* probs) {

    float part[4] = {0.f, 0.f, 0.f, 0.f};
#pragma unroll
    for (int k = 0; k < 4; k++) {
        const float* pa = (k < 3) ? A3 + (size_t)k * BH + (size_t)brow * HDIM
                                  : a3 + (size_t)brow * HDIM;
        const float* pb = nullptr;
        if (OP != MIX_ONEMINUS)
            pb = (k < 3) ? B3 + (size_t)k * BH + (size_t)brow * HDIM
                         : b3 + (size_t)brow * HDIM;
        for (int h = tid; h < HDIM; h += 256) {
            float bb = bias[k * HDIM + h];
            float c;
            if (OP == MIX_MUL)           c = pa[h] * pb[h] + bb;
            else if (OP == MIX_ADD)      c = pa[h] + pb[h] + bb;
            else if (OP == MIX_ONEMINUS) c = 1.f - (pa[h] + bb);
            else                         c = tanhf(pa[h] + pb[h] + bb);
            cs[k * HDIM + h] = c;
            part[k] += c * w[h];
        }
    }
#pragma unroll
    for (int k = 0; k < 4; k++) {
        float v = part[k];
#pragma unroll
        for (int off = 16; off > 0; off >>= 1)
            v += __shfl_xor_sync(0xffffffffu, v, off);
        if ((tid & 31) == 0) red[k][tid >> 5] = v;
    }
    __syncthreads();
    if (tid == 0) {
        float sarr[4];
#pragma unroll
        for (int k = 0; k < 4; k++) {
            float t = 0.f;
#pragma unroll
            for (int wq = 0; wq < 8; wq++) t += red[k][wq];
            sarr[k] = t;
        }
        int g = 0; float mx = sarr[0];
#pragma unroll
        for (int k = 1; k < 4; k++) if (sarr[k] > mx) { mx = sarr[k]; g = k; }
        float e[4], den = 0.f;
#pragma unroll
        for (int k = 0; k < 4; k++) { e[k] = expf(sarr[k] - mx); den += e[k]; }
#pragma unroll
        for (int k = 0; k < 4; k++) probs[k] = e[k] / den;
        if (gout) gout[(size_t)brow * 9 + gcol] = (float)g;
    }
    if (gout && gcol == 8 && tid < 3) gout[(size_t)brow * 9 + tid] = 0.f;
    __syncthreads();
    float p0 = probs[0], p1 = probs[1], p2 = probs[2], p3 = probs[3];
    for (int h = tid; h < HDIM; h += 256) {
        float v = p0 * cs[h] + p1 * cs[HDIM + h] + p2 * cs[2 * HDIM + h] +
                  p3 * cs[3 * HDIM + h];
        out[(size_t)brow * HDIM + h] = v;
        if (oh) {
            size_t o = atoff(brow, h);
            __half hh = __float2half(v);
            oh[o] = hh;
            ol[o] = __float2half(v - __half2float(hh));
        }
    }
}

template <int OP>
__global__ void __launch_bounds__(256) mix_kernel(
    const float* __restrict__ A3, const float* __restrict__ B3,
    const float* __restrict__ a3, const float* __restrict__ b3,
    const float* __restrict__ bias, const float* __restrict__ w,
    float* __restrict__ out,
    __half* __restrict__ oh, __half* __restrict__ ol,
    float* gout, int gcol) {
    __shared__ float cs[4 * HDIM];
    __shared__ float red[4][8];
    __shared__ float probs[4];
    mix_body<OP>(blockIdx.x, threadIdx.x, A3, B3, a3, b3, bias, w,
                 out, oh, ol, gout, gcol, cs, red, probs);
}

struct MixJob {
    const float *A3, *B3, *a3, *b3;
    float* out; __half *oh, *ol; int op, gcol;
};
struct MixJobs3 { MixJob j[3]; };

__global__ void __launch_bounds__(256) mix_multi(
    MixJobs3 jobs, const float* __restrict__ bias,
    const float* __restrict__ w, float* gout) {
    __shared__ float cs[4 * HDIM];
    __shared__ float red[4][8];
    __shared__ float probs[4];
    const MixJob jb = jobs.j[blockIdx.y];
    if (jb.op == MIX_MUL)
        mix_body<MIX_MUL>(blockIdx.x, threadIdx.x, jb.A3, jb.B3, jb.a3, jb.b3,
                          bias, w, jb.out, jb.oh, jb.ol, gout, jb.gcol,
                          cs, red, probs);
    else
        mix_body<MIX_ONEMINUS>(blockIdx.x, threadIdx.x, jb.A3, jb.B3, jb.a3, jb.b3,
                               bias, w, jb.out, jb.oh, jb.ol, gout, jb.gcol,
                               cs, red, probs);
}

// ---------------- orchestration ---------------------------------------------
extern "C" void kernel_launch(void* const* d_in, const int* in_sizes, int n_in,
                              void* d_out, int out_size) {
    const float* x    = (const float*)d_in[0];
    const float* hp   = (const float*)d_in[1];
    const float* L    = (const float*)d_in[2];
    const float* R    = (const float*)d_in[3];
    const float* bias = (const float*)d_in[4];
    const float* w    = (const float*)d_in[5];
    float* out = (float*)d_out;

    float* pool = nullptr;
    __half* act = nullptr;
    __half* wt  = nullptr;
    cudaGetSymbolAddress((void**)&pool, g_pool);
    cudaGetSymbolAddress((void**)&act,  g_act);
    cudaGetSymbolAddress((void**)&wt,   g_wt);
    auto P  = [&](int idx) { return pool + (size_t)idx * BH; };
    auto AB = [&](int idx) { return act + (size_t)idx * BH; };
    auto WT = [&](int m, int hl) { return wt + (size_t)(2 * m + hl) * HH; };

    cudaFuncSetAttribute(gemm_mma, cudaFuncAttributeMaxDynamicSharedMemorySize, GSMEM);

    float* Gf = nullptr;
    if ((size_t)out_size >= (size_t)BH + (size_t)BDIM * 9) Gf = out + BH;

    // preprocessing
    wsplit_kernel<<<dim3(32, 32, 6), dim3(32, 8)>>>(L, R, wt);
    asplit2_kernel<<<dim3(BH / 256, 2), 256>>>(x,  AB(A_XH),  AB(A_XL),
                                               hp, AB(A_HPH), AB(A_HPL));

    dim3 gg(8, 16, 1);

    // Stage 1: xs@L0..2, hs@R0, hs@R1
    {
        JobBatch bt;
        for (int k = 0; k < 3; k++)
            bt.j[k] = {AB(A_XH), AB(A_XL), WT(k, 0), WT(k, 1), P(P_XSL + k)};
        bt.j[3] = {AB(A_HPH), AB(A_HPL), WT(3, 0), WT(3, 1), P(P_HSR0)};
        bt.j[4] = {AB(A_HPH), AB(A_HPL), WT(4, 0), WT(4, 1), P(P_HSR1)};
        gg.z = 5;
        gemm_mma<<<gg, 256, GSMEM>>>(bt);
    }
    sig_kernel<<<BH / 256, 256>>>(P(P_XSL + 0), P(P_HSR0), P(P_XSL + 1), P(P_HSR1),
                                  bias, P(P_Z1), P(P_R),
                                  AB(A_Z1H), AB(A_Z1L), AB(A_RHI), AB(A_RLO));

    // Stage 2: hs@Lk, r@Rk, z1@Rk
    {
        JobBatch bt;
        for (int k = 0; k < 3; k++) {
            bt.j[k]     = {AB(A_HPH), AB(A_HPL), WT(k, 0),     WT(k, 1),     P(P_HSL + k)};
            bt.j[3 + k] = {AB(A_RHI), AB(A_RLO), WT(3 + k, 0), WT(3 + k, 1), P(P_RR + k)};
            bt.j[6 + k] = {AB(A_Z1H), AB(A_Z1L), WT(3 + k, 0), WT(3 + k, 1), P(P_Z1R + k)};
        }
        gg.z = 9;
        gemm_mma<<<gg, 256, GSMEM>>>(bt);
    }
    // merged: rh (g3), omz (g5), z2h (g7)
    {
        MixJobs3 mj;
        mj.j[0] = {P(P_HSL), P(P_RR),  hp,      P(P_R),  P(P_RH),  AB(A_RHH),  AB(A_RHL),  MIX_MUL,      3};
        mj.j[1] = {P(P_Z1R), nullptr,  P(P_Z1), nullptr, P(P_OMZ), AB(A_OMZH), AB(A_OMZL), MIX_ONEMINUS, 5};
        mj.j[2] = {P(P_HSL), P(P_Z1R), hp,      P(P_Z1), P(P_Z2H), AB(A_Z2HH), AB(A_Z2HL), MIX_MUL,      7};
        mix_multi<<<dim3(BDIM, 3), 256>>>(mj, bias, w, Gf);
    }

    // Stage 3: rh@Rk, omz@Rk
    {
        JobBatch bt;
        for (int k = 0; k < 3; k++) {
            bt.j[k]     = {AB(A_RHH),  AB(A_RHL),  WT(3 + k, 0), WT(3 + k, 1), P(P_RHR + k)};
            bt.j[3 + k] = {AB(A_OMZH), AB(A_OMZL), WT(3 + k, 0), WT(3 + k, 1), P(P_OMZR + k)};
        }
        gg.z = 6;
        gemm_mma<<<gg, 256, GSMEM>>>(bt);
    }
    mix_kernel<MIX_TANH><<<BDIM, 256>>>(P(P_XSL), P(P_RHR), x, P(P_RH), bias, w,
                                        P(P_HT), AB(A_HTH), AB(A_HTL), Gf, 4);

    // Stage 4: ht@Lk
    {
        JobBatch bt;
        for (int k = 0; k < 3; k++)
            bt.j[k] = {AB(A_HTH), AB(A_HTL), WT(k, 0), WT(k, 1), P(P_HTL + k)};
        gg.z = 3;
        gemm_mma<<<gg, 256, GSMEM>>>(bt);
    }
    mix_kernel<MIX_MUL><<<BDIM, 256>>>(P(P_HTL), P(P_OMZR), P(P_HT), P(P_OMZ), bias, w,
                                       P(P_ZH), AB(A_ZHH), AB(A_ZHL), Gf, 6);

    // Stage 5: zh@Lk, z2h@Rk
    {
        JobBatch bt;
        for (int k = 0; k < 3; k++) {
            bt.j[k]     = {AB(A_ZHH),  AB(A_ZHL),  WT(k, 0),     WT(k, 1),     P(P_ZHL + k)};
            bt.j[3 + k] = {AB(A_Z2HH), AB(A_Z2HL), WT(3 + k, 0), WT(3 + k, 1), P(P_Z2HR + k)};
        }
        gg.z = 6;
        gemm_mma<<<gg, 256, GSMEM>>>(bt);
    }
    mix_kernel<MIX_ADD><<<BDIM, 256>>>(P(P_ZHL), P(P_Z2HR), P(P_ZH), P(P_Z2H), bias, w,
                                       out, nullptr, nullptr, Gf, 8);
}

// round 15
// speedup vs baseline: 1.1205x; 1.1205x over previous
#include <cuda_runtime.h>
#include <cuda_fp16.h>
#include <math.h>
#include <stdint.h>

#define BDIM 2048
#define HDIM 1024
#define BH (BDIM * HDIM)
#define HH ((size_t)HDIM * HDIM)

// ---------------- fp32 scratch pool ----------------------------------------
enum {
    P_XSL  = 0,   // 3
    P_HSR0 = 3,
    P_HSR1 = 4,
    P_Z1   = 5,
    P_R    = 6,
    P_HSL  = 7,   // 3
    P_RR   = 10,  // 3
    P_Z1R  = 13,  // 3
    P_RH   = 16,
    P_OMZ  = 17,
    P_Z2H  = 18,
    P_RHR  = 19,  // 3
    P_OMZR = 22,  // 3
    P_HT   = 25,
    P_HTL  = 26,  // 3
    P_ZH   = 29,
    P_ZHL  = 30,  // 3
    P_Z2HR = 33,  // 3
    P_TOTAL = 36
};
__device__ float g_pool[(size_t)P_TOTAL * BH];

// fp16 hi/lo activation slots, K-chunk-tiled + pre-swizzled layout
enum {
    A_XH = 0, A_XL, A_HPH, A_HPL, A_Z1H, A_Z1L, A_RHI, A_RLO,
    A_RHH, A_RHL, A_OMZH, A_OMZL, A_HTH, A_HTL, A_ZHH, A_ZHL,
    A_Z2HH, A_Z2HL, A_TOTAL
};
__device__ __half g_act[(size_t)A_TOTAL * BH];

// transposed fp16 hi/lo weights, tiled layout: mat m 0..5 (L0..2,R0..2)
__device__ __half g_wt[(size_t)12 * HH];

// Tiled layout: element (row, h) -> kchunk = h/32 region of [ROWS][32],
// 64B rows, 16B chunks swizzled: chunk' = chunk ^ ((row>>1)&3).
__device__ __forceinline__ size_t toff(int row, int h, int rows) {
    return (size_t)(h >> 5) * ((size_t)rows * 32) + (size_t)row * 32 +
           (size_t)((((h >> 3) & 3) ^ ((row >> 1) & 3)) << 3) + (h & 7);
}

// ======================= PTX helpers ========================================
__device__ __forceinline__ uint32_t smem_u32(const void* p) {
    uint32_t a;
    asm("{ .reg .u64 t; cvta.to.shared.u64 t, %1; cvt.u32.u64 %0, t; }"
        : "=r"(a) : "l"(p));
    return a;
}

#define MBARRIER_INIT(mbar, count) \
    asm volatile("mbarrier.init.shared.b64 [%0], %1;" \
                 :: "r"((uint32_t)(mbar)), "r"((uint32_t)(count)) : "memory")

#define MBARRIER_EXPECT_TX(mbar, bytes) \
    asm volatile("mbarrier.arrive.expect_tx.shared.b64 _, [%0], %1;" \
                 :: "r"((uint32_t)(mbar)), "r"((uint32_t)(bytes)) : "memory")

#define MBARRIER_ARRIVE(mbar) \
    asm volatile("mbarrier.arrive.shared.b64 _, [%0];" \
                 :: "r"((uint32_t)(mbar)) : "memory")

#define MBARRIER_WAIT_PARITY(mbar, parity) do {                                   \
    uint32_t _m = (uint32_t)(mbar);                                               \
    uint32_t _p = (uint32_t)(parity);                                             \
    asm volatile(                                                                 \
        "{\n\t.reg .pred P1;\n\t"                                                 \
        "WAIT_LOOP_%=:\n\t"                                                       \
        "mbarrier.try_wait.parity.acquire.cta.shared::cta.b64 P1, [%0], %1, 0x989680;\n\t" \
        "@P1 bra.uni WAIT_DONE_%=;\n\t"                                           \
        "bra.uni WAIT_LOOP_%=;\n\t"                                               \
        "WAIT_DONE_%=:\n\t}"                                                      \
        :: "r"(_m), "r"(_p) : "memory");                                          \
} while (0)

__device__ __forceinline__ void bulk_g2s(uint32_t smem, const void* g,
                                         uint32_t bytes, uint32_t mbar) {
    asm volatile(
        "cp.async.bulk.shared::cluster.global.mbarrier::complete_tx::bytes "
        "[%0], [%1], %2, [%3];"
        :: "r"(smem), "l"(g), "r"(bytes), "r"(mbar) : "memory");
}

__device__ __forceinline__ void ldm_x4(uint32_t* r, uint32_t addr) {
    asm volatile("ldmatrix.sync.aligned.m8n8.x4.shared.b16 {%0,%1,%2,%3}, [%4];"
                 : "=r"(r[0]), "=r"(r[1]), "=r"(r[2]), "=r"(r[3]) : "r"(addr));
}

__device__ __forceinline__ void mma_f16(float* c, const uint32_t* a,
                                        uint32_t b0, uint32_t b1) {
    asm volatile(
        "mma.sync.aligned.m16n8k16.row.col.f32.f16.f16.f32 "
        "{%0,%1,%2,%3}, {%4,%5,%6,%7}, {%8,%9}, {%0,%1,%2,%3};"
        : "+f"(c[0]), "+f"(c[1]), "+f"(c[2]), "+f"(c[3])
        : "r"(a[0]), "r"(a[1]), "r"(a[2]), "r"(a[3]), "r"(b0), "r"(b1));
}

// ======================= bulk-copy batched GEMM (R13 state) ==================
// C = (Ahi+Alo) @ (Bhi+Blo)^T, 3 passes (drop lo*lo), fp16 operands, f32 accum.
struct Job {
    const __half* Ah; const __half* Al;
    const __half* Bh; const __half* Bl;
    float* C;
};
struct JobBatch { Job j[9]; };

#define KITERS  32
#define RGN     8192u          // 128 rows * 64B
#define STAGEB  32768u         // Ah + Al + Bh + Bl
#define NSTAGE  3
#define GSMEM   (128 + NSTAGE * 32768)

#define MFP_GROUP(MFP) do {                                                       \
    uint32_t ah[2][4], al[2][4];                                                  \
    _Pragma("unroll")                                                             \
    for (int q = 0; q < 2; q++) {                                                 \
        int mf = (MFP) * 2 + q;                                                   \
        int r = wm + mf * 16 + (lane & 15);                                       \
        int c = ks * 2 + (lane >> 4);                                             \
        uint32_t off = (uint32_t)r * 64u +                                        \
                       (uint32_t)((c ^ ((r >> 1) & 3)) << 4);                     \
        ldm_x4(ah[q], base + off);                                                \
        ldm_x4(al[q], base + RGN + off);                                          \
    }                                                                             \
    _Pragma("unroll")                                                             \
    for (int q = 0; q < 2; q++)                                                   \
        _Pragma("unroll")                                                         \
        for (int nf = 0; nf < 4; nf++)                                            \
            mma_f16(acc[(MFP) * 2 + q][nf], ah[q],                                \
                    bh[nf >> 1][(nf & 1) * 2], bh[nf >> 1][(nf & 1) * 2 + 1]);    \
    _Pragma("unroll")                                                             \
    for (int q = 0; q < 2; q++)                                                   \
        _Pragma("unroll")                                                         \
        for (int nf = 0; nf < 4; nf++)                                            \
            mma_f16(acc[(MFP) * 2 + q][nf], al[q],                                \
                    bh[nf >> 1][(nf & 1) * 2], bh[nf >> 1][(nf & 1) * 2 + 1]);    \
    _Pragma("unroll")                                                             \
    for (int q = 0; q < 2; q++)                                                   \
        _Pragma("unroll")                                                         \
        for (int nf = 0; nf < 4; nf++)                                            \
            mma_f16(acc[(MFP) * 2 + q][nf], ah[q],                                \
                    bl[nf >> 1][(nf & 1) * 2], bl[nf >> 1][(nf & 1) * 2 + 1]);    \
} while (0)

__global__ void __launch_bounds__(256, 2) gemm_mma(JobBatch batch) {
    extern __shared__ char dsm[];
    const Job job = batch.j[blockIdx.z];
    const int tid  = threadIdx.x;
    const int lane = tid & 31;
    const int wid  = tid >> 5;
    const int m0 = blockIdx.y * 128, n0 = blockIdx.x * 128;
    const int wm = (wid & 1) * 64;
    const int wn = (wid >> 1) * 32;

    const uint32_t sb  = smem_u32(dsm);
    const uint32_t stg = sb + 128;

    if (tid == 0) {
#pragma unroll
        for (int s = 0; s < NSTAGE; s++) {
            MBARRIER_INIT(sb + s * 16, 1);      // full: tx-based
            MBARRIER_INIT(sb + s * 16 + 8, 8);  // empty: one arrive per warp
        }
    }
    __syncthreads();

    auto issue = [&](uint32_t sOff, int kc) {
        uint32_t dst = stg + sOff * STAGEB;
        uint32_t bar = sb + sOff * 16;
        MBARRIER_EXPECT_TX(bar, STAGEB);
        size_t ao = (size_t)kc * (2048 * 32) + (size_t)m0 * 32;
        size_t bo = (size_t)kc * (1024 * 32) + (size_t)n0 * 32;
        bulk_g2s(dst,           job.Ah + ao, RGN, bar);
        bulk_g2s(dst + RGN,     job.Al + ao, RGN, bar);
        bulk_g2s(dst + 2 * RGN, job.Bh + bo, RGN, bar);
        bulk_g2s(dst + 3 * RGN, job.Bl + bo, RGN, bar);
    };

    float acc[4][4][4];
#pragma unroll
    for (int i = 0; i < 4; i++)
#pragma unroll
        for (int j = 0; j < 4; j++)
#pragma unroll
            for (int q = 0; q < 4; q++) acc[i][j][q] = 0.f;

    if (tid == 0) { issue(0, 0); issue(1, 1); issue(2, 2); }

    uint32_t s = 0;
    int phase = 0;
    const bool rev = (wid & 4) != 0;

#pragma unroll 1
    for (int it = 0; it < KITERS; ++it) {
        MBARRIER_WAIT_PARITY(sb + s * 16, phase);

        const uint32_t base = stg + s * STAGEB;
#pragma unroll
        for (int ks = 0; ks < 2; ks++) {
            uint32_t bh[2][4], bl[2][4];
#pragma unroll
            for (int p = 0; p < 2; p++) {
                int r = wn + p * 16 + ((lane >> 4) & 1) * 8 + (lane & 7);
                int c = ks * 2 + ((lane >> 3) & 1);
                uint32_t off = (uint32_t)r * 64u +
                               (uint32_t)((c ^ ((r >> 1) & 3)) << 4);
                ldm_x4(bh[p], base + 2u * RGN + off);
                ldm_x4(bl[p], base + 3u * RGN + off);
            }
            if (rev) { MFP_GROUP(1); MFP_GROUP(0); }
            else     { MFP_GROUP(0); MFP_GROUP(1); }
        }
        if (lane == 0) MBARRIER_ARRIVE(sb + s * 16 + 8);
        if (tid == 0 && it + NSTAGE < KITERS) {
            MBARRIER_WAIT_PARITY(sb + s * 16 + 8, phase);
            issue(s, it + NSTAGE);
        }
        if (++s == NSTAGE) { s = 0; phase ^= 1; }
    }

    float* C = job.C + (size_t)m0 * HDIM + n0;
    const int r4 = lane >> 2, c2 = (lane & 3) * 2;
#pragma unroll
    for (int mf = 0; mf < 4; mf++)
#pragma unroll
        for (int nf = 0; nf < 4; nf++) {
            float* p0 = C + (size_t)(wm + mf * 16 + r4) * HDIM + wn + nf * 8 + c2;
            *(float2*)p0 = make_float2(acc[mf][nf][0], acc[mf][nf][1]);
            *(float2*)(p0 + 8 * HDIM) = make_float2(acc[mf][nf][2], acc[mf][nf][3]);
        }
}

// ---------------- weight transpose + fp16 hi/lo (tiled layout) --------------
__global__ void wsplit_kernel(const float* __restrict__ L, const float* __restrict__ R,
                              __half* __restrict__ wt) {
    __shared__ float s[32][33];
    const int m = blockIdx.z;  // 0..5
    const float* W = (m < 3) ? (L + (size_t)m * HH) : (R + (size_t)(m - 3) * HH);
    __half* dh = wt + (size_t)(2 * m) * HH;
    __half* dl = wt + (size_t)(2 * m + 1) * HH;
    const int k0 = blockIdx.y * 32, n0 = blockIdx.x * 32;
    const int tx = threadIdx.x, ty = threadIdx.y;
#pragma unroll
    for (int j = 0; j < 32; j += 8)
        s[ty + j][tx] = W[(size_t)(k0 + ty + j) * HDIM + n0 + tx];
    __syncthreads();
#pragma unroll
    for (int j = 0; j < 32; j += 8) {
        float v = s[tx][ty + j];
        __half h = __float2half(v);
        size_t o = toff(n0 + ty + j, k0 + tx, 1024);
        dh[o] = h;
        dl[o] = __float2half(v - __half2float(h));
    }
}

// ---------------- activation fp16 split (tiled layout), 2 tensors -----------
__global__ void asplit2_kernel(const float* __restrict__ a0,
                               __half* __restrict__ hi0, __half* __restrict__ lo0,
                               const float* __restrict__ a1,
                               __half* __restrict__ hi1, __half* __restrict__ lo1) {
    int i = blockIdx.x * 256 + threadIdx.x;
    if (i >= BH) return;
    const float* a = blockIdx.y ? a1 : a0;
    __half* hi = blockIdx.y ? hi1 : hi0;
    __half* lo = blockIdx.y ? lo1 : lo0;
    float v = a[i];
    __half h = __float2half(v);
    size_t o = toff(i >> 10, i & 1023, 2048);
    hi[o] = h;
    lo[o] = __float2half(v - __half2float(h));
}

// ---------------- fused double sigmoid (+ tiled splits) ---------------------
__global__ void sig_kernel(const float* __restrict__ xsL0, const float* __restrict__ hsR0,
                           const float* __restrict__ xsL1, const float* __restrict__ hsR1,
                           const float* __restrict__ bias,
                           float* __restrict__ z1, float* __restrict__ r,
                           __half* __restrict__ z1h, __half* __restrict__ z1l,
                           __half* __restrict__ rh, __half* __restrict__ rl) {
    int i = blockIdx.x * blockDim.x + threadIdx.x;
    if (i >= BH) return;
    int h = i & (HDIM - 1);
    float t0 = xsL0[i] + hsR0[i] + bias[h];
    float t1 = xsL1[i] + hsR1[i] + bias[HDIM + h];
    float v0 = 1.f / (1.f + expf(-t0));
    float v1 = 1.f / (1.f + expf(-t1));
    z1[i] = v0; r[i] = v1;
    size_t o = toff(i >> 10, h, 2048);
    __half h0 = __float2half(v0);
    __half h1 = __float2half(v1);
    z1h[o] = h0; z1l[o] = __float2half(v0 - __half2float(h0));
    rh[o]  = h1; rl[o]  = __float2half(v1 - __half2float(h1));
}

// ---------------- mix kernels: register-held candidates ---------------------
enum { MIX_MUL = 0, MIX_ADD = 1, MIX_ONEMINUS = 2, MIX_TANH = 3 };

template <int OP>
__device__ __forceinline__ void mix_body(
    int brow, int tid,
    const float* __restrict__ A3, const float* __restrict__ B3,
    const float* __restrict__ a3, const float* __restrict__ b3,
    const float* __restrict__ bias, const float* __restrict__ w,
    float* __restrict__ out,
    __half* __restrict__ oh, __half* __restrict__ ol,
    float* gout, int gcol,
    float (*red)[8], float* probs) {

    // candidates held in registers: 4 k x 4 h-positions (h = tid + j*256)
    float cand[4][4];
    float part[4] = {0.f, 0.f, 0.f, 0.f};
#pragma unroll
    for (int k = 0; k < 4; k++) {
        const float* pa = (k < 3) ? A3 + (size_t)k * BH + (size_t)brow * HDIM
                                  : a3 + (size_t)brow * HDIM;
        const float* pb = nullptr;
        if (OP != MIX_ONEMINUS)
            pb = (k < 3) ? B3 + (size_t)k * BH + (size_t)brow * HDIM
                         : b3 + (size_t)brow * HDIM;
#pragma unroll
        for (int j = 0; j < 4; j++) {
            int h = tid + j * 256;
            float bb = bias[k * HDIM + h];
            float c;
            if (OP == MIX_MUL)           c = pa[h] * pb[h] + bb;
            else if (OP == MIX_ADD)      c = pa[h] + pb[h] + bb;
            else if (OP == MIX_ONEMINUS) c = 1.f - (pa[h] + bb);
            else                         c = tanhf(pa[h] + pb[h] + bb);
            cand[k][j] = c;
            part[k] += c * w[h];
        }
    }
#pragma unroll
    for (int k = 0; k < 4; k++) {
        float v = part[k];
#pragma unroll
        for (int off = 16; off > 0; off >>= 1)
            v += __shfl_xor_sync(0xffffffffu, v, off);
        if ((tid & 31) == 0) red[k][tid >> 5] = v;
    }
    __syncthreads();
    if (tid == 0) {
        float sarr[4];
#pragma unroll
        for (int k = 0; k < 4; k++) {
            float t = 0.f;
#pragma unroll
            for (int wq = 0; wq < 8; wq++) t += red[k][wq];
            sarr[k] = t;
        }
        int g = 0; float mx = sarr[0];
#pragma unroll
        for (int k = 1; k < 4; k++) if (sarr[k] > mx) { mx = sarr[k]; g = k; }
        float e[4], den = 0.f;
#pragma unroll
        for (int k = 0; k < 4; k++) { e[k] = expf(sarr[k] - mx); den += e[k]; }
#pragma unroll
        for (int k = 0; k < 4; k++) probs[k] = e[k] / den;
        if (gout) gout[(size_t)brow * 9 + gcol] = (float)g;
    }
    if (gout && gcol == 8 && tid < 3) gout[(size_t)brow * 9 + tid] = 0.f;
    __syncthreads();
    float p0 = probs[0], p1 = probs[1], p2 = probs[2], p3 = probs[3];
#pragma unroll
    for (int j = 0; j < 4; j++) {
        int h = tid + j * 256;
        float v = p0 * cand[0][j] + p1 * cand[1][j] + p2 * cand[2][j] +
                  p3 * cand[3][j];
        out[(size_t)brow * HDIM + h] = v;
        if (oh) {
            size_t o = toff(brow, h, 2048);
            __half hh = __float2half(v);
            oh[o] = hh;
            ol[o] = __float2half(v - __half2float(hh));
        }
    }
}

template <int OP>
__global__ void __launch_bounds__(256) mix_kernel(
    const float* __restrict__ A3, const float* __restrict__ B3,
    const float* __restrict__ a3, const float* __restrict__ b3,
    const float* __restrict__ bias, const float* __restrict__ w,
    float* __restrict__ out,
    __half* __restrict__ oh, __half* __restrict__ ol,
    float* gout, int gcol) {
    __shared__ float red[4][8];
    __shared__ float probs[4];
    mix_body<OP>(blockIdx.x, threadIdx.x, A3, B3, a3, b3, bias, w,
                 out, oh, ol, gout, gcol, red, probs);
}

struct MixJob {
    const float *A3, *B3, *a3, *b3;
    float* out; __half *oh, *ol; int op, gcol;
};
struct MixJobs3 { MixJob j[3]; };

__global__ void __launch_bounds__(256) mix_multi(
    MixJobs3 jobs, const float* __restrict__ bias,
    const float* __restrict__ w, float* gout) {
    __shared__ float red[4][8];
    __shared__ float probs[4];
    const MixJob jb = jobs.j[blockIdx.y];
    if (jb.op == MIX_MUL)
        mix_body<MIX_MUL>(blockIdx.x, threadIdx.x, jb.A3, jb.B3, jb.a3, jb.b3,
                          bias, w, jb.out, jb.oh, jb.ol, gout, jb.gcol,
                          red, probs);
    else
        mix_body<MIX_ONEMINUS>(blockIdx.x, threadIdx.x, jb.A3, jb.B3, jb.a3, jb.b3,
                               bias, w, jb.out, jb.oh, jb.ol, gout, jb.gcol,
                               red, probs);
}

// ---------------- orchestration ---------------------------------------------
extern "C" void kernel_launch(void* const* d_in, const int* in_sizes, int n_in,
                              void* d_out, int out_size) {
    const float* x    = (const float*)d_in[0];
    const float* hp   = (const float*)d_in[1];
    const float* L    = (const float*)d_in[2];
    const float* R    = (const float*)d_in[3];
    const float* bias = (const float*)d_in[4];
    const float* w    = (const float*)d_in[5];
    float* out = (float*)d_out;

    float* pool = nullptr;
    __half* act = nullptr;
    __half* wt  = nullptr;
    cudaGetSymbolAddress((void**)&pool, g_pool);
    cudaGetSymbolAddress((void**)&act,  g_act);
    cudaGetSymbolAddress((void**)&wt,   g_wt);
    auto P  = [&](int idx) { return pool + (size_t)idx * BH; };
    auto AB = [&](int idx) { return act + (size_t)idx * BH; };
    auto WT = [&](int m, int hl) { return wt + (size_t)(2 * m + hl) * HH; };

    cudaFuncSetAttribute(gemm_mma, cudaFuncAttributeMaxDynamicSharedMemorySize, GSMEM);

    float* Gf = nullptr;
    if ((size_t)out_size >= (size_t)BH + (size_t)BDIM * 9) Gf = out + BH;

    // preprocessing
    wsplit_kernel<<<dim3(32, 32, 6), dim3(32, 8)>>>(L, R, wt);
    asplit2_kernel<<<dim3(BH / 256, 2), 256>>>(x,  AB(A_XH),  AB(A_XL),
                                               hp, AB(A_HPH), AB(A_HPL));

    dim3 gg(8, 16, 1);

    // Stage 1: xs@L0..2, hs@R0, hs@R1
    {
        JobBatch bt;
        for (int k = 0; k < 3; k++)
            bt.j[k] = {AB(A_XH), AB(A_XL), WT(k, 0), WT(k, 1), P(P_XSL + k)};
        bt.j[3] = {AB(A_HPH), AB(A_HPL), WT(3, 0), WT(3, 1), P(P_HSR0)};
        bt.j[4] = {AB(A_HPH), AB(A_HPL), WT(4, 0), WT(4, 1), P(P_HSR1)};
        gg.z = 5;
        gemm_mma<<<gg, 256, GSMEM>>>(bt);
    }
    sig_kernel<<<BH / 256, 256>>>(P(P_XSL + 0), P(P_HSR0), P(P_XSL + 1), P(P_HSR1),
                                  bias, P(P_Z1), P(P_R),
                                  AB(A_Z1H), AB(A_Z1L), AB(A_RHI), AB(A_RLO));

    // Stage 2: hs@Lk, r@Rk, z1@Rk
    {
        JobBatch bt;
        for (int k = 0; k < 3; k++) {
            bt.j[k]     = {AB(A_HPH), AB(A_HPL), WT(k, 0),     WT(k, 1),     P(P_HSL + k)};
            bt.j[3 + k] = {AB(A_RHI), AB(A_RLO), WT(3 + k, 0), WT(3 + k, 1), P(P_RR + k)};
            bt.j[6 + k] = {AB(A_Z1H), AB(A_Z1L), WT(3 + k, 0), WT(3 + k, 1), P(P_Z1R + k)};
        }
        gg.z = 9;
        gemm_mma<<<gg, 256, GSMEM>>>(bt);
    }
    // merged: rh (g3), omz (g5), z2h (g7)
    {
        MixJobs3 mj;
        mj.j[0] = {P(P_HSL), P(P_RR),  hp,      P(P_R),  P(P_RH),  AB(A_RHH),  AB(A_RHL),  MIX_MUL,      3};
        mj.j[1] = {P(P_Z1R), nullptr,  P(P_Z1), nullptr, P(P_OMZ), AB(A_OMZH), AB(A_OMZL), MIX_ONEMINUS, 5};
        mj.j[2] = {P(P_HSL), P(P_Z1R), hp,      P(P_Z1), P(P_Z2H), AB(A_Z2HH), AB(A_Z2HL), MIX_MUL,      7};
        mix_multi<<<dim3(BDIM, 3), 256>>>(mj, bias, w, Gf);
    }

    // Stage 3: rh@Rk, omz@Rk
    {
        JobBatch bt;
        for (int k = 0; k < 3; k++) {
            bt.j[k]     = {AB(A_RHH),  AB(A_RHL),  WT(3 + k, 0), WT(3 + k, 1), P(P_RHR + k)};
            bt.j[3 + k] = {AB(A_OMZH), AB(A_OMZL), WT(3 + k, 0), WT(3 + k, 1), P(P_OMZR + k)};
        }
        gg.z = 6;
        gemm_mma<<<gg, 256, GSMEM>>>(bt);
    }
    mix_kernel<MIX_TANH><<<BDIM, 256>>>(P(P_XSL), P(P_RHR), x, P(P_RH), bias, w,
                                        P(P_HT), AB(A_HTH), AB(A_HTL), Gf, 4);

    // Stage 4: ht@Lk
    {
        JobBatch bt;
        for (int k = 0; k < 3; k++)
            bt.j[k] = {AB(A_HTH), AB(A_HTL), WT(k, 0), WT(k, 1), P(P_HTL + k)};
        gg.z = 3;
        gemm_mma<<<gg, 256, GSMEM>>>(bt);
    }
    mix_kernel<MIX_MUL><<<BDIM, 256>>>(P(P_HTL), P(P_OMZR), P(P_HT), P(P_OMZ), bias, w,
                                       P(P_ZH), AB(A_ZHH), AB(A_ZHL), Gf, 6);

    // Stage 5: zh@Lk, z2h@Rk
    {
        JobBatch bt;
        for (int k = 0; k < 3; k++) {
            bt.j[k]     = {AB(A_ZHH),  AB(A_ZHL),  WT(k, 0),     WT(k, 1),     P(P_ZHL + k)};
            bt.j[3 + k] = {AB(A_Z2HH), AB(A_Z2HL), WT(3 + k, 0), WT(3 + k, 1), P(P_Z2HR + k)};
        }
        gg.z = 6;
        gemm_mma<<<gg, 256, GSMEM>>>(bt);
    }
    mix_kernel<MIX_ADD><<<BDIM, 256>>>(P(P_ZHL), P(P_Z2HR), P(P_ZH), P(P_Z2H), bias, w,
                                       out, nullptr, nullptr, Gf, 8);
}

// round 16
// speedup vs baseline: 1.1558x; 1.0315x over previous
#include <cuda_runtime.h>
#include <cuda_fp16.h>
#include <math.h>
#include <stdint.h>

#define BDIM 2048
#define HDIM 1024
#define BH (BDIM * HDIM)
#define HH ((size_t)HDIM * HDIM)

// ---------------- fp32 scratch pool ----------------------------------------
enum {
    P_XSL  = 0,   // 3
    P_HSR0 = 3,
    P_HSR1 = 4,
    P_Z1   = 5,
    P_R    = 6,
    P_HSL  = 7,   // 3
    P_RR   = 10,  // 3
    P_Z1R  = 13,  // 3
    P_RH   = 16,
    P_OMZ  = 17,
    P_Z2H  = 18,
    P_RHR  = 19,  // 3
    P_OMZR = 22,  // 3
    P_HT   = 25,
    P_HTL  = 26,  // 3
    P_ZH   = 29,
    P_ZHL  = 30,  // 3
    P_Z2HR = 33,  // 3
    P_TOTAL = 36
};
__device__ float g_pool[(size_t)P_TOTAL * BH];

// fp16 hi/lo activation slots, K-chunk-tiled + pre-swizzled layout
enum {
    A_XH = 0, A_XL, A_HPH, A_HPL, A_Z1H, A_Z1L, A_RHI, A_RLO,
    A_RHH, A_RHL, A_OMZH, A_OMZL, A_HTH, A_HTL, A_ZHH, A_ZHL,
    A_Z2HH, A_Z2HL, A_TOTAL
};
__device__ __half g_act[(size_t)A_TOTAL * BH];

// transposed fp16 hi/lo weights, tiled layout: mat m 0..5 (L0..2,R0..2)
__device__ __half g_wt[(size_t)12 * HH];

// Tiled layout: element (row, h) -> kchunk = h/32 region of [ROWS][32],
// 64B rows, 16B chunks swizzled: chunk' = chunk ^ ((row>>1)&3).
__device__ __forceinline__ size_t toff(int row, int h, int rows) {
    return (size_t)(h >> 5) * ((size_t)rows * 32) + (size_t)row * 32 +
           (size_t)((((h >> 3) & 3) ^ ((row >> 1) & 3)) << 3) + (h & 7);
}

// ======================= PTX helpers ========================================
__device__ __forceinline__ uint32_t smem_u32(const void* p) {
    uint32_t a;
    asm("{ .reg .u64 t; cvta.to.shared.u64 t, %1; cvt.u32.u64 %0, t; }"
        : "=r"(a) : "l"(p));
    return a;
}

#define MBARRIER_INIT(mbar, count) \
    asm volatile("mbarrier.init.shared.b64 [%0], %1;" \
                 :: "r"((uint32_t)(mbar)), "r"((uint32_t)(count)) : "memory")

#define MBARRIER_EXPECT_TX(mbar, bytes) \
    asm volatile("mbarrier.arrive.expect_tx.shared.b64 _, [%0], %1;" \
                 :: "r"((uint32_t)(mbar)), "r"((uint32_t)(bytes)) : "memory")

#define MBARRIER_ARRIVE(mbar) \
    asm volatile("mbarrier.arrive.shared.b64 _, [%0];" \
                 :: "r"((uint32_t)(mbar)) : "memory")

#define MBARRIER_WAIT_PARITY(mbar, parity) do {                                   \
    uint32_t _m = (uint32_t)(mbar);                                               \
    uint32_t _p = (uint32_t)(parity);                                             \
    asm volatile(                                                                 \
        "{\n\t.reg .pred P1;\n\t"                                                 \
        "WAIT_LOOP_%=:\n\t"                                                       \
        "mbarrier.try_wait.parity.acquire.cta.shared::cta.b64 P1, [%0], %1, 0x989680;\n\t" \
        "@P1 bra.uni WAIT_DONE_%=;\n\t"                                           \
        "bra.uni WAIT_LOOP_%=;\n\t"                                               \
        "WAIT_DONE_%=:\n\t}"                                                      \
        :: "r"(_m), "r"(_p) : "memory");                                          \
} while (0)

__device__ __forceinline__ void bulk_g2s(uint32_t smem, const void* g,
                                         uint32_t bytes, uint32_t mbar) {
    asm volatile(
        "cp.async.bulk.shared::cluster.global.mbarrier::complete_tx::bytes "
        "[%0], [%1], %2, [%3];"
        :: "r"(smem), "l"(g), "r"(bytes), "r"(mbar) : "memory");
}

__device__ __forceinline__ void ldm_x4(uint32_t* r, uint32_t addr) {
    asm volatile("ldmatrix.sync.aligned.m8n8.x4.shared.b16 {%0,%1,%2,%3}, [%4];"
                 : "=r"(r[0]), "=r"(r[1]), "=r"(r[2]), "=r"(r[3]) : "r"(addr));
}

__device__ __forceinline__ void mma_f16(float* c, const uint32_t* a,
                                        uint32_t b0, uint32_t b1) {
    asm volatile(
        "mma.sync.aligned.m16n8k16.row.col.f32.f16.f16.f32 "
        "{%0,%1,%2,%3}, {%4,%5,%6,%7}, {%8,%9}, {%0,%1,%2,%3};"
        : "+f"(c[0]), "+f"(c[1]), "+f"(c[2]), "+f"(c[3])
        : "r"(a[0]), "r"(a[1]), "r"(a[2]), "r"(a[3]), "r"(b0), "r"(b1));
}

// ======================= bulk-copy batched GEMM (R13/R15 state) ==============
// C = (Ahi+Alo) @ (Bhi+Blo)^T, 3 passes (drop lo*lo), fp16 operands, f32 accum.
struct Job {
    const __half* Ah; const __half* Al;
    const __half* Bh; const __half* Bl;
    float* C;
};
struct JobBatch { Job j[9]; };

#define KITERS  32
#define RGN     8192u          // 128 rows * 64B
#define STAGEB  32768u         // Ah + Al + Bh + Bl
#define NSTAGE  3
#define GSMEM   (128 + NSTAGE * 32768)

#define MFP_GROUP(MFP) do {                                                       \
    uint32_t ah[2][4], al[2][4];                                                  \
    _Pragma("unroll")                                                             \
    for (int q = 0; q < 2; q++) {                                                 \
        int mf = (MFP) * 2 + q;                                                   \
        int r = wm + mf * 16 + (lane & 15);                                       \
        int c = ks * 2 + (lane >> 4);                                             \
        uint32_t off = (uint32_t)r * 64u +                                        \
                       (uint32_t)((c ^ ((r >> 1) & 3)) << 4);                     \
        ldm_x4(ah[q], base + off);                                                \
        ldm_x4(al[q], base + RGN + off);                                          \
    }                                                                             \
    _Pragma("unroll")                                                             \
    for (int q = 0; q < 2; q++)                                                   \
        _Pragma("unroll")                                                         \
        for (int nf = 0; nf < 4; nf++)                                            \
            mma_f16(acc[(MFP) * 2 + q][nf], ah[q],                                \
                    bh[nf >> 1][(nf & 1) * 2], bh[nf >> 1][(nf & 1) * 2 + 1]);    \
    _Pragma("unroll")                                                             \
    for (int q = 0; q < 2; q++)                                                   \
        _Pragma("unroll")                                                         \
        for (int nf = 0; nf < 4; nf++)                                            \
            mma_f16(acc[(MFP) * 2 + q][nf], al[q],                                \
                    bh[nf >> 1][(nf & 1) * 2], bh[nf >> 1][(nf & 1) * 2 + 1]);    \
    _Pragma("unroll")                                                             \
    for (int q = 0; q < 2; q++)                                                   \
        _Pragma("unroll")                                                         \
        for (int nf = 0; nf < 4; nf++)                                            \
            mma_f16(acc[(MFP) * 2 + q][nf], ah[q],                                \
                    bl[nf >> 1][(nf & 1) * 2], bl[nf >> 1][(nf & 1) * 2 + 1]);    \
} while (0)

__global__ void __launch_bounds__(256, 2) gemm_mma(JobBatch batch) {
    extern __shared__ char dsm[];
    const Job job = batch.j[blockIdx.z];
    const int tid  = threadIdx.x;
    const int lane = tid & 31;
    const int wid  = tid >> 5;
    const int m0 = blockIdx.y * 128, n0 = blockIdx.x * 128;
    const int wm = (wid & 1) * 64;
    const int wn = (wid >> 1) * 32;

    const uint32_t sb  = smem_u32(dsm);
    const uint32_t stg = sb + 128;

    if (tid == 0) {
#pragma unroll
        for (int s = 0; s < NSTAGE; s++) {
            MBARRIER_INIT(sb + s * 16, 1);      // full: tx-based
            MBARRIER_INIT(sb + s * 16 + 8, 8);  // empty: one arrive per warp
        }
    }
    __syncthreads();

    auto issue = [&](uint32_t sOff, int kc) {
        uint32_t dst = stg + sOff * STAGEB;
        uint32_t bar = sb + sOff * 16;
        MBARRIER_EXPECT_TX(bar, STAGEB);
        size_t ao = (size_t)kc * (2048 * 32) + (size_t)m0 * 32;
        size_t bo = (size_t)kc * (1024 * 32) + (size_t)n0 * 32;
        bulk_g2s(dst,           job.Ah + ao, RGN, bar);
        bulk_g2s(dst + RGN,     job.Al + ao, RGN, bar);
        bulk_g2s(dst + 2 * RGN, job.Bh + bo, RGN, bar);
        bulk_g2s(dst + 3 * RGN, job.Bl + bo, RGN, bar);
    };

    float acc[4][4][4];
#pragma unroll
    for (int i = 0; i < 4; i++)
#pragma unroll
        for (int j = 0; j < 4; j++)
#pragma unroll
            for (int q = 0; q < 4; q++) acc[i][j][q] = 0.f;

    if (tid == 0) { issue(0, 0); issue(1, 1); issue(2, 2); }

    uint32_t s = 0;
    int phase = 0;
    const bool rev = (wid & 4) != 0;

#pragma unroll 1
    for (int it = 0; it < KITERS; ++it) {
        MBARRIER_WAIT_PARITY(sb + s * 16, phase);

        const uint32_t base = stg + s * STAGEB;
#pragma unroll
        for (int ks = 0; ks < 2; ks++) {
            uint32_t bh[2][4], bl[2][4];
#pragma unroll
            for (int p = 0; p < 2; p++) {
                int r = wn + p * 16 + ((lane >> 4) & 1) * 8 + (lane & 7);
                int c = ks * 2 + ((lane >> 3) & 1);
                uint32_t off = (uint32_t)r * 64u +
                               (uint32_t)((c ^ ((r >> 1) & 3)) << 4);
                ldm_x4(bh[p], base + 2u * RGN + off);
                ldm_x4(bl[p], base + 3u * RGN + off);
            }
            if (rev) { MFP_GROUP(1); MFP_GROUP(0); }
            else     { MFP_GROUP(0); MFP_GROUP(1); }
        }
        if (lane == 0) MBARRIER_ARRIVE(sb + s * 16 + 8);
        if (tid == 0 && it + NSTAGE < KITERS) {
            MBARRIER_WAIT_PARITY(sb + s * 16 + 8, phase);
            issue(s, it + NSTAGE);
        }
        if (++s == NSTAGE) { s = 0; phase ^= 1; }
    }

    float* C = job.C + (size_t)m0 * HDIM + n0;
    const int r4 = lane >> 2, c2 = (lane & 3) * 2;
#pragma unroll
    for (int mf = 0; mf < 4; mf++)
#pragma unroll
        for (int nf = 0; nf < 4; nf++) {
            float* p0 = C + (size_t)(wm + mf * 16 + r4) * HDIM + wn + nf * 8 + c2;
            *(float2*)p0 = make_float2(acc[mf][nf][0], acc[mf][nf][1]);
            *(float2*)(p0 + 8 * HDIM) = make_float2(acc[mf][nf][2], acc[mf][nf][3]);
        }
}

// ---------------- weight transpose + fp16 hi/lo (tiled layout) --------------
__global__ void wsplit_kernel(const float* __restrict__ L, const float* __restrict__ R,
                              __half* __restrict__ wt) {
    __shared__ float s[32][33];
    const int m = blockIdx.z;  // 0..5
    const float* W = (m < 3) ? (L + (size_t)m * HH) : (R + (size_t)(m - 3) * HH);
    __half* dh = wt + (size_t)(2 * m) * HH;
    __half* dl = wt + (size_t)(2 * m + 1) * HH;
    const int k0 = blockIdx.y * 32, n0 = blockIdx.x * 32;
    const int tx = threadIdx.x, ty = threadIdx.y;
#pragma unroll
    for (int j = 0; j < 32; j += 8)
        s[ty + j][tx] = W[(size_t)(k0 + ty + j) * HDIM + n0 + tx];
    __syncthreads();
#pragma unroll
    for (int j = 0; j < 32; j += 8) {
        float v = s[tx][ty + j];
        __half h = __float2half(v);
        size_t o = toff(n0 + ty + j, k0 + tx, 1024);
        dh[o] = h;
        dl[o] = __float2half(v - __half2float(h));
    }
}

// ---------------- activation fp16 split (tiled layout), 2 tensors -----------
__global__ void asplit2_kernel(const float* __restrict__ a0,
                               __half* __restrict__ hi0, __half* __restrict__ lo0,
                               const float* __restrict__ a1,
                               __half* __restrict__ hi1, __half* __restrict__ lo1) {
    int i = blockIdx.x * 256 + threadIdx.x;
    if (i >= BH) return;
    const float* a = blockIdx.y ? a1 : a0;
    __half* hi = blockIdx.y ? hi1 : hi0;
    __half* lo = blockIdx.y ? lo1 : lo0;
    float v = a[i];
    __half h = __float2half(v);
    size_t o = toff(i >> 10, i & 1023, 2048);
    hi[o] = h;
    lo[o] = __float2half(v - __half2float(h));
}

// ---------------- fused double sigmoid (+ tiled splits) ---------------------
__global__ void sig_kernel(const float* __restrict__ xsL0, const float* __restrict__ hsR0,
                           const float* __restrict__ xsL1, const float* __restrict__ hsR1,
                           const float* __restrict__ bias,
                           float* __restrict__ z1, float* __restrict__ r,
                           __half* __restrict__ z1h, __half* __restrict__ z1l,
                           __half* __restrict__ rh, __half* __restrict__ rl) {
    int i = blockIdx.x * blockDim.x + threadIdx.x;
    if (i >= BH) return;
    int h = i & (HDIM - 1);
    float t0 = xsL0[i] + hsR0[i] + bias[h];
    float t1 = xsL1[i] + hsR1[i] + bias[HDIM + h];
    float v0 = 1.f / (1.f + expf(-t0));
    float v1 = 1.f / (1.f + expf(-t1));
    z1[i] = v0; r[i] = v1;
    size_t o = toff(i >> 10, h, 2048);
    __half h0 = __float2half(v0);
    __half h1 = __float2half(v1);
    z1h[o] = h0; z1l[o] = __float2half(v0 - __half2float(h0));
    rh[o]  = h1; rl[o]  = __float2half(v1 - __half2float(h1));
}

// ---------------- mix kernels: register-held candidates ---------------------
enum { MIX_MUL = 0, MIX_ADD = 1, MIX_ONEMINUS = 2, MIX_TANH = 3 };

template <int OP>
__device__ __forceinline__ void mix_body(
    int brow, int tid,
    const float* __restrict__ A3, const float* __restrict__ B3,
    const float* __restrict__ a3, const float* __restrict__ b3,
    const float* __restrict__ bias, const float* __restrict__ w,
    float* __restrict__ out,
    __half* __restrict__ oh, __half* __restrict__ ol,
    float* gout, int gcol,
    float (*red)[8], float* probs) {

    float cand[4][4];
    float part[4] = {0.f, 0.f, 0.f, 0.f};
#pragma unroll
    for (int k = 0; k < 4; k++) {
        const float* pa = (k < 3) ? A3 + (size_t)k * BH + (size_t)brow * HDIM
                                  : a3 + (size_t)brow * HDIM;
        const float* pb = nullptr;
        if (OP != MIX_ONEMINUS)
            pb = (k < 3) ? B3 + (size_t)k * BH + (size_t)brow * HDIM
                         : b3 + (size_t)brow * HDIM;
#pragma unroll
        for (int j = 0; j < 4; j++) {
            int h = tid + j * 256;
            float bb = bias[k * HDIM + h];
            float c;
            if (OP == MIX_MUL)           c = pa[h] * pb[h] + bb;
            else if (OP == MIX_ADD)      c = pa[h] + pb[h] + bb;
            else if (OP == MIX_ONEMINUS) c = 1.f - (pa[h] + bb);
            else                         c = tanhf(pa[h] + pb[h] + bb);
            cand[k][j] = c;
            part[k] += c * w[h];
        }
    }
#pragma unroll
    for (int k = 0; k < 4; k++) {
        float v = part[k];
#pragma unroll
        for (int off = 16; off > 0; off >>= 1)
            v += __shfl_xor_sync(0xffffffffu, v, off);
        if ((tid & 31) == 0) red[k][tid >> 5] = v;
    }
    __syncthreads();
    if (tid == 0) {
        float sarr[4];
#pragma unroll
        for (int k = 0; k < 4; k++) {
            float t = 0.f;
#pragma unroll
            for (int wq = 0; wq < 8; wq++) t += red[k][wq];
            sarr[k] = t;
        }
        int g = 0; float mx = sarr[0];
#pragma unroll
        for (int k = 1; k < 4; k++) if (sarr[k] > mx) { mx = sarr[k]; g = k; }
        float e[4], den = 0.f;
#pragma unroll
        for (int k = 0; k < 4; k++) { e[k] = expf(sarr[k] - mx); den += e[k]; }
#pragma unroll
        for (int k = 0; k < 4; k++) probs[k] = e[k] / den;
        if (gout) gout[(size_t)brow * 9 + gcol] = (float)g;
    }
    if (gout && gcol == 8 && tid < 3) gout[(size_t)brow * 9 + tid] = 0.f;
    __syncthreads();
    float p0 = probs[0], p1 = probs[1], p2 = probs[2], p3 = probs[3];
#pragma unroll
    for (int j = 0; j < 4; j++) {
        int h = tid + j * 256;
        float v = p0 * cand[0][j] + p1 * cand[1][j] + p2 * cand[2][j] +
                  p3 * cand[3][j];
        out[(size_t)brow * HDIM + h] = v;
        if (oh) {
            size_t o = toff(brow, h, 2048);
            __half hh = __float2half(v);
            oh[o] = hh;
            ol[o] = __float2half(v - __half2float(hh));
        }
    }
}

template <int OP>
__global__ void __launch_bounds__(256) mix_kernel(
    const float* __restrict__ A3, const float* __restrict__ B3,
    const float* __restrict__ a3, const float* __restrict__ b3,
    const float* __restrict__ bias, const float* __restrict__ w,
    float* __restrict__ out,
    __half* __restrict__ oh, __half* __restrict__ ol,
    float* gout, int gcol) {
    __shared__ float red[4][8];
    __shared__ float probs[4];
    mix_body<OP>(blockIdx.x, threadIdx.x, A3, B3, a3, b3, bias, w,
                 out, oh, ol, gout, gcol, red, probs);
}

struct MixJob {
    const float *A3, *B3, *a3, *b3;
    float* out; __half *oh, *ol; int op, gcol;
};
struct MixJobs3 { MixJob j[3]; };

__global__ void __launch_bounds__(256) mix_multi(
    MixJobs3 jobs, const float* __restrict__ bias,
    const float* __restrict__ w, float* gout) {
    __shared__ float red[4][8];
    __shared__ float probs[4];
    const MixJob jb = jobs.j[blockIdx.y];
    if (jb.op == MIX_MUL)
        mix_body<MIX_MUL>(blockIdx.x, threadIdx.x, jb.A3, jb.B3, jb.a3, jb.b3,
                          bias, w, jb.out, jb.oh, jb.ol, gout, jb.gcol,
                          red, probs);
    else
        mix_body<MIX_ONEMINUS>(blockIdx.x, threadIdx.x, jb.A3, jb.B3, jb.a3, jb.b3,
                               bias, w, jb.out, jb.oh, jb.ol, gout, jb.gcol,
                               red, probs);
}

// ---------------- orchestration (2-stream DAG) --------------------------------
extern "C" void kernel_launch(void* const* d_in, const int* in_sizes, int n_in,
                              void* d_out, int out_size) {
    const float* x    = (const float*)d_in[0];
    const float* hp   = (const float*)d_in[1];
    const float* L    = (const float*)d_in[2];
    const float* R    = (const float*)d_in[3];
    const float* bias = (const float*)d_in[4];
    const float* w    = (const float*)d_in[5];
    float* out = (float*)d_out;

    float* pool = nullptr;
    __half* act = nullptr;
    __half* wt  = nullptr;
    cudaGetSymbolAddress((void**)&pool, g_pool);
    cudaGetSymbolAddress((void**)&act,  g_act);
    cudaGetSymbolAddress((void**)&wt,   g_wt);
    auto P  = [&](int idx) { return pool + (size_t)idx * BH; };
    auto AB = [&](int idx) { return act + (size_t)idx * BH; };
    auto WT = [&](int m, int hl) { return wt + (size_t)(2 * m + hl) * HH; };

    // lazily-created side stream + events (host resources only; GPU work
    // enqueued per call is identical every call)
    static cudaStream_t sB = nullptr;
    static cudaEvent_t evPre, evB1, evMix, evB2;
    if (!sB) {
        cudaStreamCreateWithFlags(&sB, cudaStreamNonBlocking);
        cudaEventCreateWithFlags(&evPre, cudaEventDisableTiming);
        cudaEventCreateWithFlags(&evB1,  cudaEventDisableTiming);
        cudaEventCreateWithFlags(&evMix, cudaEventDisableTiming);
        cudaEventCreateWithFlags(&evB2,  cudaEventDisableTiming);
    }

    cudaFuncSetAttribute(gemm_mma, cudaFuncAttributeMaxDynamicSharedMemorySize, GSMEM);

    float* Gf = nullptr;
    if ((size_t)out_size >= (size_t)BH + (size_t)BDIM * 9) Gf = out + BH;

    dim3 gg(8, 16, 1);

    // preprocessing (main stream)
    wsplit_kernel<<<dim3(32, 32, 6), dim3(32, 8)>>>(L, R, wt);
    asplit2_kernel<<<dim3(BH / 256, 2), 256>>>(x,  AB(A_XH),  AB(A_XL),
                                               hp, AB(A_HPH), AB(A_HPL));
    cudaEventRecord(evPre, 0);

    // ---- side stream branch 1: xs@L2, hs@L0..2 (needed only by mix_multi/g4)
    cudaStreamWaitEvent(sB, evPre, 0);
    {
        JobBatch bt;
        bt.j[0] = {AB(A_XH),  AB(A_XL),  WT(2, 0), WT(2, 1), P(P_XSL + 2)};
        for (int k = 0; k < 3; k++)
            bt.j[1 + k] = {AB(A_HPH), AB(A_HPL), WT(k, 0), WT(k, 1), P(P_HSL + k)};
        gg.z = 4;
        gemm_mma<<<gg, 256, GSMEM, sB>>>(bt);
    }
    cudaEventRecord(evB1, sB);

    // ---- main: xs@L0, xs@L1, hs@R0, hs@R1 -> sig
    {
        JobBatch bt;
        bt.j[0] = {AB(A_XH),  AB(A_XL),  WT(0, 0), WT(0, 1), P(P_XSL + 0)};
        bt.j[1] = {AB(A_XH),  AB(A_XL),  WT(1, 0), WT(1, 1), P(P_XSL + 1)};
        bt.j[2] = {AB(A_HPH), AB(A_HPL), WT(3, 0), WT(3, 1), P(P_HSR0)};
        bt.j[3] = {AB(A_HPH), AB(A_HPL), WT(4, 0), WT(4, 1), P(P_HSR1)};
        gg.z = 4;
        gemm_mma<<<gg, 256, GSMEM>>>(bt);
    }
    sig_kernel<<<BH / 256, 256>>>(P(P_XSL + 0), P(P_HSR0), P(P_XSL + 1), P(P_HSR1),
                                  bias, P(P_Z1), P(P_R),
                                  AB(A_Z1H), AB(A_Z1L), AB(A_RHI), AB(A_RLO));

    // ---- main: r@Rk, z1@Rk
    {
        JobBatch bt;
        for (int k = 0; k < 3; k++) {
            bt.j[k]     = {AB(A_RHI), AB(A_RLO), WT(3 + k, 0), WT(3 + k, 1), P(P_RR + k)};
            bt.j[3 + k] = {AB(A_Z1H), AB(A_Z1L), WT(3 + k, 0), WT(3 + k, 1), P(P_Z1R + k)};
        }
        gg.z = 6;
        gemm_mma<<<gg, 256, GSMEM>>>(bt);
    }

    // join branch 1, then merged mixes: rh (g3), omz (g5), z2h (g7)
    cudaStreamWaitEvent(0, evB1, 0);
    {
        MixJobs3 mj;
        mj.j[0] = {P(P_HSL), P(P_RR),  hp,      P(P_R),  P(P_RH),  AB(A_RHH),  AB(A_RHL),  MIX_MUL,      3};
        mj.j[1] = {P(P_Z1R), nullptr,  P(P_Z1), nullptr, P(P_OMZ), AB(A_OMZH), AB(A_OMZL), MIX_ONEMINUS, 5};
        mj.j[2] = {P(P_HSL), P(P_Z1R), hp,      P(P_Z1), P(P_Z2H), AB(A_Z2HH), AB(A_Z2HL), MIX_MUL,      7};
        mix_multi<<<dim3(BDIM, 3), 256>>>(mj, bias, w, Gf);
    }
    cudaEventRecord(evMix, 0);

    // ---- side stream branch 2: z2h@Rk (depends only on g7) -----------------
    cudaStreamWaitEvent(sB, evMix, 0);
    {
        JobBatch bt;
        for (int k = 0; k < 3; k++)
            bt.j[k] = {AB(A_Z2HH), AB(A_Z2HL), WT(3 + k, 0), WT(3 + k, 1), P(P_Z2HR + k)};
        gg.z = 3;
        gemm_mma<<<gg, 256, GSMEM, sB>>>(bt);
    }
    cudaEventRecord(evB2, sB);

    // ---- main chain: rh@Rk, omz@Rk -> g4 -> ht@Lk -> g6 -> zh@Lk ------------
    {
        JobBatch bt;
        for (int k = 0; k < 3; k++) {
            bt.j[k]     = {AB(A_RHH),  AB(A_RHL),  WT(3 + k, 0), WT(3 + k, 1), P(P_RHR + k)};
            bt.j[3 + k] = {AB(A_OMZH), AB(A_OMZL), WT(3 + k, 0), WT(3 + k, 1), P(P_OMZR + k)};
        }
        gg.z = 6;
        gemm_mma<<<gg, 256, GSMEM>>>(bt);
    }
    mix_kernel<MIX_TANH><<<BDIM, 256>>>(P(P_XSL), P(P_RHR), x, P(P_RH), bias, w,
                                        P(P_HT), AB(A_HTH), AB(A_HTL), Gf, 4);
    {
        JobBatch bt;
        for (int k = 0; k < 3; k++)
            bt.j[k] = {AB(A_HTH), AB(A_HTL), WT(k, 0), WT(k, 1), P(P_HTL + k)};
        gg.z = 3;
        gemm_mma<<<gg, 256, GSMEM>>>(bt);
    }
    mix_kernel<MIX_MUL><<<BDIM, 256>>>(P(P_HTL), P(P_OMZR), P(P_HT), P(P_OMZ), bias, w,
                                       P(P_ZH), AB(A_ZHH), AB(A_ZHL), Gf, 6);
    {
        JobBatch bt;
        for (int k = 0; k < 3; k++)
            bt.j[k] = {AB(A_ZHH), AB(A_ZHL), WT(k, 0), WT(k, 1), P(P_ZHL + k)};
        gg.z = 3;
        gemm_mma<<<gg, 256, GSMEM>>>(bt);
    }

    // join branch 2, final mix: h_next (g8)
    cudaStreamWaitEvent(0, evB2, 0);
    mix_kernel<MIX_ADD><<<BDIM, 256>>>(P(P_ZHL), P(P_Z2HR), P(P_ZH), P(P_Z2H), bias, w,
                                       out, nullptr, nullptr, Gf, 8);
}

// round 17
// speedup vs baseline: 1.1681x; 1.0107x over previous
#include <cuda_runtime.h>
#include <cuda_fp16.h>
#include <math.h>
#include <stdint.h>

#define BDIM 2048
#define HDIM 1024
#define BH (BDIM * HDIM)
#define HH ((size_t)HDIM * HDIM)

// ---------------- fp32 scratch pool ----------------------------------------
enum {
    P_XSL  = 0,   // 3
    P_HSR0 = 3,
    P_HSR1 = 4,
    P_Z1   = 5,
    P_R    = 6,
    P_HSL  = 7,   // 3
    P_RR   = 10,  // 3
    P_Z1R  = 13,  // 3
    P_RH   = 16,
    P_OMZ  = 17,
    P_Z2H  = 18,
    P_RHR  = 19,  // 3
    P_OMZR = 22,  // 3
    P_HT   = 25,
    P_HTL  = 26,  // 3
    P_ZH   = 29,
    P_ZHL  = 30,  // 3
    P_Z2HR = 33,  // 3
    P_TOTAL = 36
};
__device__ float g_pool[(size_t)P_TOTAL * BH];

// fp16 hi/lo activation slots, K-chunk-tiled + pre-swizzled layout
enum {
    A_XH = 0, A_XL, A_HPH, A_HPL, A_Z1H, A_Z1L, A_RHI, A_RLO,
    A_RHH, A_RHL, A_OMZH, A_OMZL, A_HTH, A_HTL, A_ZHH, A_ZHL,
    A_Z2HH, A_Z2HL, A_TOTAL
};
__device__ __half g_act[(size_t)A_TOTAL * BH];

// transposed fp16 hi/lo weights, tiled layout: mat m 0..5 (L0..2,R0..2)
__device__ __half g_wt[(size_t)12 * HH];

// Tiled layout: element (row, h) -> kchunk = h/32 region of [ROWS][32],
// 64B rows, 16B chunks swizzled: chunk' = chunk ^ ((row>>1)&3).
__device__ __forceinline__ size_t toff(int row, int h, int rows) {
    return (size_t)(h >> 5) * ((size_t)rows * 32) + (size_t)row * 32 +
           (size_t)((((h >> 3) & 3) ^ ((row >> 1) & 3)) << 3) + (h & 7);
}

// ======================= PTX helpers ========================================
__device__ __forceinline__ uint32_t smem_u32(const void* p) {
    uint32_t a;
    asm("{ .reg .u64 t; cvta.to.shared.u64 t, %1; cvt.u32.u64 %0, t; }"
        : "=r"(a) : "l"(p));
    return a;
}

#define MBARRIER_INIT(mbar, count) \
    asm volatile("mbarrier.init.shared.b64 [%0], %1;" \
                 :: "r"((uint32_t)(mbar)), "r"((uint32_t)(count)) : "memory")

#define MBARRIER_EXPECT_TX(mbar, bytes) \
    asm volatile("mbarrier.arrive.expect_tx.shared.b64 _, [%0], %1;" \
                 :: "r"((uint32_t)(mbar)), "r"((uint32_t)(bytes)) : "memory")

#define MBARRIER_ARRIVE(mbar) \
    asm volatile("mbarrier.arrive.shared.b64 _, [%0];" \
                 :: "r"((uint32_t)(mbar)) : "memory")

#define MBARRIER_WAIT_PARITY(mbar, parity) do {                                   \
    uint32_t _m = (uint32_t)(mbar);                                               \
    uint32_t _p = (uint32_t)(parity);                                             \
    asm volatile(                                                                 \
        "{\n\t.reg .pred P1;\n\t"                                                 \
        "WAIT_LOOP_%=:\n\t"                                                       \
        "mbarrier.try_wait.parity.acquire.cta.shared::cta.b64 P1, [%0], %1, 0x989680;\n\t" \
        "@P1 bra.uni WAIT_DONE_%=;\n\t"                                           \
        "bra.uni WAIT_LOOP_%=;\n\t"                                               \
        "WAIT_DONE_%=:\n\t}"                                                      \
        :: "r"(_m), "r"(_p) : "memory");                                          \
} while (0)

__device__ __forceinline__ void bulk_g2s(uint32_t smem, const void* g,
                                         uint32_t bytes, uint32_t mbar) {
    asm volatile(
        "cp.async.bulk.shared::cluster.global.mbarrier::complete_tx::bytes "
        "[%0], [%1], %2, [%3];"
        :: "r"(smem), "l"(g), "r"(bytes), "r"(mbar) : "memory");
}

__device__ __forceinline__ void ldm_x4(uint32_t* r, uint32_t addr) {
    asm volatile("ldmatrix.sync.aligned.m8n8.x4.shared.b16 {%0,%1,%2,%3}, [%4];"
                 : "=r"(r[0]), "=r"(r[1]), "=r"(r[2]), "=r"(r[3]) : "r"(addr));
}

__device__ __forceinline__ void mma_f16(float* c, const uint32_t* a,
                                        uint32_t b0, uint32_t b1) {
    asm volatile(
        "mma.sync.aligned.m16n8k16.row.col.f32.f16.f16.f32 "
        "{%0,%1,%2,%3}, {%4,%5,%6,%7}, {%8,%9}, {%0,%1,%2,%3};"
        : "+f"(c[0]), "+f"(c[1]), "+f"(c[2]), "+f"(c[3])
        : "r"(a[0]), "r"(a[1]), "r"(a[2]), "r"(a[3]), "r"(b0), "r"(b1));
}

// ======================= bulk-copy batched GEMM (stable core) ================
// C = (Ahi+Alo) @ (Bhi+Blo)^T, 3 passes (drop lo*lo), fp16 operands, f32 accum.
struct Job {
    const __half* Ah; const __half* Al;
    const __half* Bh; const __half* Bl;
    float* C;
};
struct JobBatch { Job j[9]; };

#define KITERS  32
#define RGN     8192u          // 128 rows * 64B
#define STAGEB  32768u         // Ah + Al + Bh + Bl
#define NSTAGE  3
#define GSMEM   (128 + NSTAGE * 32768)

#define MFP_GROUP(MFP) do {                                                       \
    uint32_t ah[2][4], al[2][4];                                                  \
    _Pragma("unroll")                                                             \
    for (int q = 0; q < 2; q++) {                                                 \
        int mf = (MFP) * 2 + q;                                                   \
        int r = wm + mf * 16 + (lane & 15);                                       \
        int c = ks * 2 + (lane >> 4);                                             \
        uint32_t off = (uint32_t)r * 64u +                                        \
                       (uint32_t)((c ^ ((r >> 1) & 3)) << 4);                     \
        ldm_x4(ah[q], base + off);                                                \
        ldm_x4(al[q], base + RGN + off);                                          \
    }                                                                             \
    _Pragma("unroll")                                                             \
    for (int q = 0; q < 2; q++)                                                   \
        _Pragma("unroll")                                                         \
        for (int nf = 0; nf < 4; nf++)                                            \
            mma_f16(acc[(MFP) * 2 + q][nf], ah[q],                                \
                    bh[nf >> 1][(nf & 1) * 2], bh[nf >> 1][(nf & 1) * 2 + 1]);    \
    _Pragma("unroll")                                                             \
    for (int q = 0; q < 2; q++)                                                   \
        _Pragma("unroll")                                                         \
        for (int nf = 0; nf < 4; nf++)                                            \
            mma_f16(acc[(MFP) * 2 + q][nf], al[q],                                \
                    bh[nf >> 1][(nf & 1) * 2], bh[nf >> 1][(nf & 1) * 2 + 1]);    \
    _Pragma("unroll")                                                             \
    for (int q = 0; q < 2; q++)                                                   \
        _Pragma("unroll")                                                         \
        for (int nf = 0; nf < 4; nf++)                                            \
            mma_f16(acc[(MFP) * 2 + q][nf], ah[q],                                \
                    bl[nf >> 1][(nf & 1) * 2], bl[nf >> 1][(nf & 1) * 2 + 1]);    \
} while (0)

__global__ void __launch_bounds__(256, 2) gemm_mma(JobBatch batch) {
    extern __shared__ char dsm[];
    const Job job = batch.j[blockIdx.z];
    const int tid  = threadIdx.x;
    const int lane = tid & 31;
    const int wid  = tid >> 5;
    const int m0 = blockIdx.y * 128, n0 = blockIdx.x * 128;
    const int wm = (wid & 1) * 64;
    const int wn = (wid >> 1) * 32;

    const uint32_t sb  = smem_u32(dsm);
    const uint32_t stg = sb + 128;

    if (tid == 0) {
#pragma unroll
        for (int s = 0; s < NSTAGE; s++) {
            MBARRIER_INIT(sb + s * 16, 1);      // full: tx-based
            MBARRIER_INIT(sb + s * 16 + 8, 8);  // empty: one arrive per warp
        }
    }
    __syncthreads();

    auto issue = [&](uint32_t sOff, int kc) {
        uint32_t dst = stg + sOff * STAGEB;
        uint32_t bar = sb + sOff * 16;
        MBARRIER_EXPECT_TX(bar, STAGEB);
        size_t ao = (size_t)kc * (2048 * 32) + (size_t)m0 * 32;
        size_t bo = (size_t)kc * (1024 * 32) + (size_t)n0 * 32;
        bulk_g2s(dst,           job.Ah + ao, RGN, bar);
        bulk_g2s(dst + RGN,     job.Al + ao, RGN, bar);
        bulk_g2s(dst + 2 * RGN, job.Bh + bo, RGN, bar);
        bulk_g2s(dst + 3 * RGN, job.Bl + bo, RGN, bar);
    };

    float acc[4][4][4];
#pragma unroll
    for (int i = 0; i < 4; i++)
#pragma unroll
        for (int j = 0; j < 4; j++)
#pragma unroll
            for (int q = 0; q < 4; q++) acc[i][j][q] = 0.f;

    if (tid == 0) { issue(0, 0); issue(1, 1); issue(2, 2); }

    uint32_t s = 0;
    int phase = 0;
    const bool rev = (wid & 4) != 0;

#pragma unroll 1
    for (int it = 0; it < KITERS; ++it) {
        MBARRIER_WAIT_PARITY(sb + s * 16, phase);

        const uint32_t base = stg + s * STAGEB;
#pragma unroll
        for (int ks = 0; ks < 2; ks++) {
            uint32_t bh[2][4], bl[2][4];
#pragma unroll
            for (int p = 0; p < 2; p++) {
                int r = wn + p * 16 + ((lane >> 4) & 1) * 8 + (lane & 7);
                int c = ks * 2 + ((lane >> 3) & 1);
                uint32_t off = (uint32_t)r * 64u +
                               (uint32_t)((c ^ ((r >> 1) & 3)) << 4);
                ldm_x4(bh[p], base + 2u * RGN + off);
                ldm_x4(bl[p], base + 3u * RGN + off);
            }
            if (rev) { MFP_GROUP(1); MFP_GROUP(0); }
            else     { MFP_GROUP(0); MFP_GROUP(1); }
        }
        if (lane == 0) MBARRIER_ARRIVE(sb + s * 16 + 8);
        if (tid == 0 && it + NSTAGE < KITERS) {
            MBARRIER_WAIT_PARITY(sb + s * 16 + 8, phase);
            issue(s, it + NSTAGE);
        }
        if (++s == NSTAGE) { s = 0; phase ^= 1; }
    }

    float* C = job.C + (size_t)m0 * HDIM + n0;
    const int r4 = lane >> 2, c2 = (lane & 3) * 2;
#pragma unroll
    for (int mf = 0; mf < 4; mf++)
#pragma unroll
        for (int nf = 0; nf < 4; nf++) {
            float* p0 = C + (size_t)(wm + mf * 16 + r4) * HDIM + wn + nf * 8 + c2;
            *(float2*)p0 = make_float2(acc[mf][nf][0], acc[mf][nf][1]);
            *(float2*)(p0 + 8 * HDIM) = make_float2(acc[mf][nf][2], acc[mf][nf][3]);
        }
}

// ---------------- weight transpose + fp16 hi/lo (tiled layout) --------------
__global__ void wsplit_kernel(const float* __restrict__ L, const float* __restrict__ R,
                              __half* __restrict__ wt) {
    __shared__ float s[32][33];
    const int m = blockIdx.z;  // 0..5
    const float* W = (m < 3) ? (L + (size_t)m * HH) : (R + (size_t)(m - 3) * HH);
    __half* dh = wt + (size_t)(2 * m) * HH;
    __half* dl = wt + (size_t)(2 * m + 1) * HH;
    const int k0 = blockIdx.y * 32, n0 = blockIdx.x * 32;
    const int tx = threadIdx.x, ty = threadIdx.y;
#pragma unroll
    for (int j = 0; j < 32; j += 8)
        s[ty + j][tx] = W[(size_t)(k0 + ty + j) * HDIM + n0 + tx];
    __syncthreads();
#pragma unroll
    for (int j = 0; j < 32; j += 8) {
        float v = s[tx][ty + j];
        __half h = __float2half(v);
        size_t o = toff(n0 + ty + j, k0 + tx, 1024);
        dh[o] = h;
        dl[o] = __float2half(v - __half2float(h));
    }
}

// ---------------- activation fp16 split, x2 vectorized ----------------------
__global__ void asplit2_kernel(const float* __restrict__ a0,
                               __half* __restrict__ hi0, __half* __restrict__ lo0,
                               const float* __restrict__ a1,
                               __half* __restrict__ hi1, __half* __restrict__ lo1) {
    int i = (blockIdx.x * 256 + threadIdx.x) * 2;
    if (i >= BH) return;
    const float* a = blockIdx.y ? a1 : a0;
    __half* hi = blockIdx.y ? hi1 : hi0;
    __half* lo = blockIdx.y ? lo1 : lo0;
    float2 v = *(const float2*)(a + i);
    __half h0 = __float2half(v.x), h1 = __float2half(v.y);
    size_t o = toff(i >> 10, i & 1023, 2048);   // h even -> (h,h+1) contiguous
    *(__half2*)(hi + o) = __halves2half2(h0, h1);
    *(__half2*)(lo + o) = __halves2half2(
        __float2half(v.x - __half2float(h0)), __float2half(v.y - __half2float(h1)));
}

// ---------------- fused double sigmoid, x2 vectorized -----------------------
__global__ void sig_kernel(const float* __restrict__ xsL0, const float* __restrict__ hsR0,
                           const float* __restrict__ xsL1, const float* __restrict__ hsR1,
                           const float* __restrict__ bias,
                           float* __restrict__ z1, float* __restrict__ r,
                           __half* __restrict__ z1h, __half* __restrict__ z1l,
                           __half* __restrict__ rh, __half* __restrict__ rl) {
    int i = (blockIdx.x * blockDim.x + threadIdx.x) * 2;
    if (i >= BH) return;
    int h = i & (HDIM - 1);
    float2 a0 = *(const float2*)(xsL0 + i);
    float2 b0 = *(const float2*)(hsR0 + i);
    float2 a1 = *(const float2*)(xsL1 + i);
    float2 b1 = *(const float2*)(hsR1 + i);
    float2 bb0 = *(const float2*)(bias + h);
    float2 bb1 = *(const float2*)(bias + HDIM + h);
    float v0x = 1.f / (1.f + expf(-(a0.x + b0.x + bb0.x)));
    float v0y = 1.f / (1.f + expf(-(a0.y + b0.y + bb0.y)));
    float v1x = 1.f / (1.f + expf(-(a1.x + b1.x + bb1.x)));
    float v1y = 1.f / (1.f + expf(-(a1.y + b1.y + bb1.y)));
    *(float2*)(z1 + i) = make_float2(v0x, v0y);
    *(float2*)(r + i)  = make_float2(v1x, v1y);
    size_t o = toff(i >> 10, h, 2048);
    __half h0x = __float2half(v0x), h0y = __float2half(v0y);
    __half h1x = __float2half(v1x), h1y = __float2half(v1y);
    *(__half2*)(z1h + o) = __halves2half2(h0x, h0y);
    *(__half2*)(z1l + o) = __halves2half2(
        __float2half(v0x - __half2float(h0x)), __float2half(v0y - __half2float(h0y)));
    *(__half2*)(rh + o) = __halves2half2(h1x, h1y);
    *(__half2*)(rl + o) = __halves2half2(
        __float2half(v1x - __half2float(h1x)), __float2half(v1y - __half2float(h1y)));
}

// ---------------- mix kernels: register-held candidates ---------------------
enum { MIX_MUL = 0, MIX_ADD = 1, MIX_ONEMINUS = 2, MIX_TANH = 3 };

template <int OP>
__device__ __forceinline__ void mix_body(
    int brow, int tid,
    const float* __restrict__ A3, const float* __restrict__ B3,
    const float* __restrict__ a3, const float* __restrict__ b3,
    const float* __restrict__ bias, const float* __restrict__ w,
    float* __restrict__ out,
    __half* __restrict__ oh, __half* __restrict__ ol,
    float* gout, int gcol,
    float (*red)[8], float* probs) {

    float cand[4][4];
    float part[4] = {0.f, 0.f, 0.f, 0.f};
#pragma unroll
    for (int k = 0; k < 4; k++) {
        const float* pa = (k < 3) ? A3 + (size_t)k * BH + (size_t)brow * HDIM
                                  : a3 + (size_t)brow * HDIM;
        const float* pb = nullptr;
        if (OP != MIX_ONEMINUS)
            pb = (k < 3) ? B3 + (size_t)k * BH + (size_t)brow * HDIM
                         : b3 + (size_t)brow * HDIM;
#pragma unroll
        for (int j = 0; j < 4; j++) {
            int h = tid + j * 256;
            float bb = bias[k * HDIM + h];
            float c;
            if (OP == MIX_MUL)           c = pa[h] * pb[h] + bb;
            else if (OP == MIX_ADD)      c = pa[h] + pb[h] + bb;
            else if (OP == MIX_ONEMINUS) c = 1.f - (pa[h] + bb);
            else                         c = tanhf(pa[h] + pb[h] + bb);
            cand[k][j] = c;
            part[k] += c * w[h];
        }
    }
#pragma unroll
    for (int k = 0; k < 4; k++) {
        float v = part[k];
#pragma unroll
        for (int off = 16; off > 0; off >>= 1)
            v += __shfl_xor_sync(0xffffffffu, v, off);
        if ((tid & 31) == 0) red[k][tid >> 5] = v;
    }
    __syncthreads();
    if (tid == 0) {
        float sarr[4];
#pragma unroll
        for (int k = 0; k < 4; k++) {
            float t = 0.f;
#pragma unroll
            for (int wq = 0; wq < 8; wq++) t += red[k][wq];
            sarr[k] = t;
        }
        int g = 0; float mx = sarr[0];
#pragma unroll
        for (int k = 1; k < 4; k++) if (sarr[k] > mx) { mx = sarr[k]; g = k; }
        float e[4], den = 0.f;
#pragma unroll
        for (int k = 0; k < 4; k++) { e[k] = expf(sarr[k] - mx); den += e[k]; }
#pragma unroll
        for (int k = 0; k < 4; k++) probs[k] = e[k] / den;
        if (gout) gout[(size_t)brow * 9 + gcol] = (float)g;
    }
    if (gout && gcol == 8 && tid < 3) gout[(size_t)brow * 9 + tid] = 0.f;
    __syncthreads();
    float p0 = probs[0], p1 = probs[1], p2 = probs[2], p3 = probs[3];
#pragma unroll
    for (int j = 0; j < 4; j++) {
        int h = tid + j * 256;
        float v = p0 * cand[0][j] + p1 * cand[1][j] + p2 * cand[2][j] +
                  p3 * cand[3][j];
        out[(size_t)brow * HDIM + h] = v;
        if (oh) {
            size_t o = toff(brow, h, 2048);
            __half hh = __float2half(v);
            oh[o] = hh;
            ol[o] = __float2half(v - __half2float(hh));
        }
    }
}

template <int OP>
__global__ void __launch_bounds__(256) mix_kernel(
    const float* __restrict__ A3, const float* __restrict__ B3,
    const float* __restrict__ a3, const float* __restrict__ b3,
    const float* __restrict__ bias, const float* __restrict__ w,
    float* __restrict__ out,
    __half* __restrict__ oh, __half* __restrict__ ol,
    float* gout, int gcol) {
    __shared__ float red[4][8];
    __shared__ float probs[4];
    mix_body<OP>(blockIdx.x, threadIdx.x, A3, B3, a3, b3, bias, w,
                 out, oh, ol, gout, gcol, red, probs);
}

struct MixJob {
    const float *A3, *B3, *a3, *b3;
    float* out; __half *oh, *ol; int op, gcol;
};
struct MixJobs3 { MixJob j[3]; };

__global__ void __launch_bounds__(256) mix_multi(
    MixJobs3 jobs, const float* __restrict__ bias,
    const float* __restrict__ w, float* gout) {
    __shared__ float red[4][8];
    __shared__ float probs[4];
    const MixJob jb = jobs.j[blockIdx.y];
    if (jb.op == MIX_MUL)
        mix_body<MIX_MUL>(blockIdx.x, threadIdx.x, jb.A3, jb.B3, jb.a3, jb.b3,
                          bias, w, jb.out, jb.oh, jb.ol, gout, jb.gcol,
                          red, probs);
    else
        mix_body<MIX_ONEMINUS>(blockIdx.x, threadIdx.x, jb.A3, jb.B3, jb.a3, jb.b3,
                               bias, w, jb.out, jb.oh, jb.ol, gout, jb.gcol,
                               red, probs);
}

// ---------------- orchestration (balanced 2-stream DAG) -----------------------
extern "C" void kernel_launch(void* const* d_in, const int* in_sizes, int n_in,
                              void* d_out, int out_size) {
    const float* x    = (const float*)d_in[0];
    const float* hp   = (const float*)d_in[1];
    const float* L    = (const float*)d_in[2];
    const float* R    = (const float*)d_in[3];
    const float* bias = (const float*)d_in[4];
    const float* w    = (const float*)d_in[5];
    float* out = (float*)d_out;

    float* pool = nullptr;
    __half* act = nullptr;
    __half* wt  = nullptr;
    cudaGetSymbolAddress((void**)&pool, g_pool);
    cudaGetSymbolAddress((void**)&act,  g_act);
    cudaGetSymbolAddress((void**)&wt,   g_wt);
    auto P  = [&](int idx) { return pool + (size_t)idx * BH; };
    auto AB = [&](int idx) { return act + (size_t)idx * BH; };
    auto WT = [&](int m, int hl) { return wt + (size_t)(2 * m + hl) * HH; };

    static cudaStream_t sB = nullptr;
    static cudaEvent_t evPre, evB1, evMix, evB2;
    if (!sB) {
        cudaStreamCreateWithFlags(&sB, cudaStreamNonBlocking);
        cudaEventCreateWithFlags(&evPre, cudaEventDisableTiming);
        cudaEventCreateWithFlags(&evB1,  cudaEventDisableTiming);
        cudaEventCreateWithFlags(&evMix, cudaEventDisableTiming);
        cudaEventCreateWithFlags(&evB2,  cudaEventDisableTiming);
    }

    cudaFuncSetAttribute(gemm_mma, cudaFuncAttributeMaxDynamicSharedMemorySize, GSMEM);

    float* Gf = nullptr;
    if ((size_t)out_size >= (size_t)BH + (size_t)BDIM * 9) Gf = out + BH;

    dim3 gg(8, 16, 1);

    // preprocessing (main stream)
    wsplit_kernel<<<dim3(32, 32, 6), dim3(32, 8)>>>(L, R, wt);
    asplit2_kernel<<<dim3(BH / 512, 2), 256>>>(x,  AB(A_XH),  AB(A_XL),
                                               hp, AB(A_HPH), AB(A_HPL));
    cudaEventRecord(evPre, 0);

    // ---- side branch 1: xs@L2, hs@L0..2 (needed only by mix_multi / g4) ----
    cudaStreamWaitEvent(sB, evPre, 0);
    {
        JobBatch bt;
        bt.j[0] = {AB(A_XH),  AB(A_XL),  WT(2, 0), WT(2, 1), P(P_XSL + 2)};
        for (int k = 0; k < 3; k++)
            bt.j[1 + k] = {AB(A_HPH), AB(A_HPL), WT(k, 0), WT(k, 1), P(P_HSL + k)};
        gg.z = 4;
        gemm_mma<<<gg, 256, GSMEM, sB>>>(bt);
    }
    cudaEventRecord(evB1, sB);

    // ---- main: xs@L0, xs@L1, hs@R0, hs@R1 -> sig
    {
        JobBatch bt;
        bt.j[0] = {AB(A_XH),  AB(A_XL),  WT(0, 0), WT(0, 1), P(P_XSL + 0)};
        bt.j[1] = {AB(A_XH),  AB(A_XL),  WT(1, 0), WT(1, 1), P(P_XSL + 1)};
        bt.j[2] = {AB(A_HPH), AB(A_HPL), WT(3, 0), WT(3, 1), P(P_HSR0)};
        bt.j[3] = {AB(A_HPH), AB(A_HPL), WT(4, 0), WT(4, 1), P(P_HSR1)};
        gg.z = 4;
        gemm_mma<<<gg, 256, GSMEM>>>(bt);
    }
    sig_kernel<<<BH / 512, 256>>>(P(P_XSL + 0), P(P_HSR0), P(P_XSL + 1), P(P_HSR1),
                                  bias, P(P_Z1), P(P_R),
                                  AB(A_Z1H), AB(A_Z1L), AB(A_RHI), AB(A_RLO));

    // ---- main: r@Rk, z1@Rk
    {
        JobBatch bt;
        for (int k = 0; k < 3; k++) {
            bt.j[k]     = {AB(A_RHI), AB(A_RLO), WT(3 + k, 0), WT(3 + k, 1), P(P_RR + k)};
            bt.j[3 + k] = {AB(A_Z1H), AB(A_Z1L), WT(3 + k, 0), WT(3 + k, 1), P(P_Z1R + k)};
        }
        gg.z = 6;
        gemm_mma<<<gg, 256, GSMEM>>>(bt);
    }

    // join branch 1, merged mixes: rh (g3), omz (g5), z2h (g7)
    cudaStreamWaitEvent(0, evB1, 0);
    {
        MixJobs3 mj;
        mj.j[0] = {P(P_HSL), P(P_RR),  hp,      P(P_R),  P(P_RH),  AB(A_RHH),  AB(A_RHL),  MIX_MUL,      3};
        mj.j[1] = {P(P_Z1R), nullptr,  P(P_Z1), nullptr, P(P_OMZ), AB(A_OMZH), AB(A_OMZL), MIX_ONEMINUS, 5};
        mj.j[2] = {P(P_HSL), P(P_Z1R), hp,      P(P_Z1), P(P_Z2H), AB(A_Z2HH), AB(A_Z2HL), MIX_MUL,      7};
        mix_multi<<<dim3(BDIM, 3), 256>>>(mj, bias, w, Gf);
    }
    cudaEventRecord(evMix, 0);

    // ---- side branch 2: z2h@Rk + omz@Rk (off the critical path) ------------
    cudaStreamWaitEvent(sB, evMix, 0);
    {
        JobBatch bt;
        for (int k = 0; k < 3; k++) {
            bt.j[k]     = {AB(A_Z2HH), AB(A_Z2HL), WT(3 + k, 0), WT(3 + k, 1), P(P_Z2HR + k)};
            bt.j[3 + k] = {AB(A_OMZH), AB(A_OMZL), WT(3 + k, 0), WT(3 + k, 1), P(P_OMZR + k)};
        }
        gg.z = 6;
        gemm_mma<<<gg, 256, GSMEM, sB>>>(bt);
    }
    cudaEventRecord(evB2, sB);

    // ---- main critical chain: rh@Rk -> g4 -> ht@Lk -> g6 -> zh@Lk ----------
    {
        JobBatch bt;
        for (int k = 0; k < 3; k++)
            bt.j[k] = {AB(A_RHH), AB(A_RHL), WT(3 + k, 0), WT(3 + k, 1), P(P_RHR + k)};
        gg.z = 3;
        gemm_mma<<<gg, 256, GSMEM>>>(bt);
    }
    mix_kernel<MIX_TANH><<<BDIM, 256>>>(P(P_XSL), P(P_RHR), x, P(P_RH), bias, w,
                                        P(P_HT), AB(A_HTH), AB(A_HTL), Gf, 4);
    {
        JobBatch bt;
        for (int k = 0; k < 3; k++)
            bt.j[k] = {AB(A_HTH), AB(A_HTL), WT(k, 0), WT(k, 1), P(P_HTL + k)};
        gg.z = 3;
        gemm_mma<<<gg, 256, GSMEM>>>(bt);
    }
    cudaStreamWaitEvent(0, evB2, 0);  // need OMZR for g6 (also covers Z2HR for g8)
    mix_kernel<MIX_MUL><<<BDIM, 256>>>(P(P_HTL), P(P_OMZR), P(P_HT), P(P_OMZ), bias, w,
                                       P(P_ZH), AB(A_ZHH), AB(A_ZHL), Gf, 6);
    {
        JobBatch bt;
        for (int k = 0; k < 3; k++)
            bt.j[k] = {AB(A_ZHH), AB(A_ZHL), WT(k, 0), WT(k, 1), P(P_ZHL + k)};
        gg.z = 3;
        gemm_mma<<<gg, 256, GSMEM>>>(bt);
    }

    // final mix: h_next (g8)
    mix_kernel<MIX_ADD><<<BDIM, 256>>>(P(P_ZHL), P(P_Z2HR), P(P_ZH), P(P_Z2H), bias, w,
                                       out, nullptr, nullptr, Gf, 8);
}